// round 1
// baseline (speedup 1.0000x reference)
#include <cuda_runtime.h>
#include <math.h>

// Problem constants
#define Bn     4
#define Tn     8192
#define DA     1024
#define DS     64
#define CHUNKL 128
#define NCHUNK 64            // Tn / CHUNKL
#define ROWS   (Bn * Tn)     // 32768
#define LN_EPS 1e-5f

// ---------------- scratch (__device__ globals; no allocation) ----------------
__device__ float g_xshift[(size_t)ROWS * DA];   // 128 MB
__device__ float g_kv[(size_t)ROWS * 2 * DS];   // 16 MB  (k | v per row)
__device__ float g_wkv[(size_t)ROWS * DS];      // 8 MB
__device__ float g_hs[(size_t)ROWS * DS];       // 8 MB
__device__ float g_mu[ROWS];
__device__ float g_rstd[ROWS];
__device__ float g_w[DS];
__device__ float g_etf[DS];
__device__ float g_coef[CHUNKL * DS];           // impulse response of intra stride-scan
__device__ float g_coef2[NCHUNK * DS];          // impulse response of chunk stride-scan

// ---------------- prep: w, exp(tf), stride-scan impulse responses -----------
__global__ void k_prep(const float* __restrict__ td, const float* __restrict__ tf) {
    int d = threadIdx.x;
    if (d >= DS) return;
    float w = expf(td[d]);
    g_w[d]   = w;
    g_etf[d] = expf(tf[d]);

    // impulse response of _stride_scan with S=CHUNKL:
    // apply (I + w*R_s) for s=1..S-1 to impulse at 0; read final vector.
    float c[CHUNKL];
    c[0] = 1.0f;
    for (int i = 1; i < CHUNKL; i++) c[i] = 0.0f;
    for (int s = 1; s < CHUNKL; s++)
        for (int i = CHUNKL - 1; i >= s; i--)
            c[i] += w * c[i - s];
    for (int i = 0; i < CHUNKL; i++) g_coef[i * DS + d] = c[i];

    float W = expf((float)CHUNKL * td[d]);  // w^CHUNK
    float c2[NCHUNK];
    c2[0] = 1.0f;
    for (int i = 1; i < NCHUNK; i++) c2[i] = 0.0f;
    for (int s = 1; s < NCHUNK; s++)
        for (int i = NCHUNK - 1; i >= s; i--)
            c2[i] += W * c2[i - s];
    for (int i = 0; i < NCHUNK; i++) g_coef2[i * DS + d] = c2[i];
}

// ---------------- GEMM config ----------------
#define BM 128
#define BN 128
#define BK 8
#define TM 8
#define TN 8
// 256 threads: ty = tid/16 (0..15), tx = tid%16 (0..15)

// GEMM1: x_shift = (x_rolled @ Wshift) * gate + x * (1-gate)
__global__ __launch_bounds__(256) void k_gemm1(const float* __restrict__ x,
                                               const float* __restrict__ Wsh,
                                               const float* __restrict__ sgate) {
    __shared__ float As[BK][BM];
    __shared__ float Bs[BK][BN];

    int tid = threadIdx.x;
    int rowBase = blockIdx.y * BM;
    int nBase   = blockIdx.x * BN;
    int ty = tid >> 4, tx = tid & 15;

    int arow = tid >> 1;            // 0..127
    int acol = (tid & 1) * 4;       // 0 or 4
    int brow = tid >> 5;            // 0..7
    int bcol = (tid & 31) * 4;      // 0..124

    float acc[TM][TN];
#pragma unroll
    for (int i = 0; i < TM; i++)
#pragma unroll
        for (int j = 0; j < TN; j++) acc[i][j] = 0.0f;

    int srcrow = (rowBase + arow) ^ 4096;   // x_cat row remap (T=8192, sl=4096)
    const float* Aptr = x + (size_t)srcrow * DA;

    for (int kb = 0; kb < DA; kb += BK) {
        float4 av = *reinterpret_cast<const float4*>(Aptr + kb + acol);
        As[acol + 0][arow] = av.x;
        As[acol + 1][arow] = av.y;
        As[acol + 2][arow] = av.z;
        As[acol + 3][arow] = av.w;
        float4 bv = *reinterpret_cast<const float4*>(Wsh + (size_t)(kb + brow) * DA + nBase + bcol);
        *reinterpret_cast<float4*>(&Bs[brow][bcol]) = bv;
        __syncthreads();

#pragma unroll
        for (int k = 0; k < BK; k++) {
            float a[TM], b[TN];
#pragma unroll
            for (int i = 0; i < TM; i++) a[i] = As[k][ty * TM + i];
#pragma unroll
            for (int j = 0; j < TN; j++) b[j] = Bs[k][tx * TN + j];
#pragma unroll
            for (int i = 0; i < TM; i++)
#pragma unroll
                for (int j = 0; j < TN; j++) acc[i][j] = fmaf(a[i], b[j], acc[i][j]);
        }
        __syncthreads();
    }

    // epilogue: gate mix
    float gv[TN];
#pragma unroll
    for (int j = 0; j < TN; j++) {
        int n = nBase + tx * TN + j;
        gv[j] = 1.0f / (1.0f + expf(-sgate[n]));
    }
#pragma unroll
    for (int i = 0; i < TM; i++) {
        int r = rowBase + ty * TM + i;
#pragma unroll
        for (int j = 0; j < TN; j++) {
            int n = nBase + tx * TN + j;
            float xv = x[(size_t)r * DA + n];
            g_xshift[(size_t)r * DA + n] = acc[i][j] * gv[j] + xv * (1.0f - gv[j]);
        }
    }
}

// ---------------- LayerNorm stats ----------------
__global__ __launch_bounds__(256) void k_lnstats() {
    int r = blockIdx.x;
    const float* xr = g_xshift + (size_t)r * DA;
    float s = 0.0f, s2 = 0.0f;
    for (int i = threadIdx.x; i < DA; i += 256) {
        float v = xr[i];
        s += v;
        s2 = fmaf(v, v, s2);
    }
#pragma unroll
    for (int o = 16; o > 0; o >>= 1) {
        s  += __shfl_down_sync(0xffffffffu, s, o);
        s2 += __shfl_down_sync(0xffffffffu, s2, o);
    }
    __shared__ float ss[8], ss2[8];
    int w = threadIdx.x >> 5;
    if ((threadIdx.x & 31) == 0) { ss[w] = s; ss2[w] = s2; }
    __syncthreads();
    if (threadIdx.x == 0) {
        float S = 0.0f, S2 = 0.0f;
#pragma unroll
        for (int i = 0; i < 8; i++) { S += ss[i]; S2 += ss2[i]; }
        float mu  = S / (float)DA;
        float var = S2 / (float)DA - mu * mu;
        g_mu[r]   = mu;
        g_rstd[r] = rsqrtf(var + LN_EPS);
    }
}

// GEMM2: [k|v] = layernorm(x_shift) @ [Wk|Wv]   (N = 128, normalization fused in A load)
__global__ __launch_bounds__(256) void k_gemm2(const float* __restrict__ Wk,
                                               const float* __restrict__ Wv,
                                               const float* __restrict__ lng,
                                               const float* __restrict__ lnb) {
    __shared__ float As[BK][BM];
    __shared__ float Bs[BK][BN];

    int tid = threadIdx.x;
    int rowBase = blockIdx.y * BM;
    int ty = tid >> 4, tx = tid & 15;

    int arow = tid >> 1;
    int acol = (tid & 1) * 4;
    int brow = tid >> 5;
    int bcol = (tid & 31) * 4;

    float acc[TM][TN];
#pragma unroll
    for (int i = 0; i < TM; i++)
#pragma unroll
        for (int j = 0; j < TN; j++) acc[i][j] = 0.0f;

    int gr = rowBase + arow;
    float mu = g_mu[gr], rstd = g_rstd[gr];
    const float* Aptr = g_xshift + (size_t)gr * DA;

    for (int kb = 0; kb < DA; kb += BK) {
        float4 av = *reinterpret_cast<const float4*>(Aptr + kb + acol);
        float4 gv = *reinterpret_cast<const float4*>(lng + kb + acol);
        float4 bvv = *reinterpret_cast<const float4*>(lnb + kb + acol);
        As[acol + 0][arow] = (av.x - mu) * rstd * gv.x + bvv.x;
        As[acol + 1][arow] = (av.y - mu) * rstd * gv.y + bvv.y;
        As[acol + 2][arow] = (av.z - mu) * rstd * gv.z + bvv.z;
        As[acol + 3][arow] = (av.w - mu) * rstd * gv.w + bvv.w;
        float4 bv;
        if (bcol < DS)
            bv = *reinterpret_cast<const float4*>(Wk + (size_t)(kb + brow) * DS + bcol);
        else
            bv = *reinterpret_cast<const float4*>(Wv + (size_t)(kb + brow) * DS + (bcol - DS));
        *reinterpret_cast<float4*>(&Bs[brow][bcol]) = bv;
        __syncthreads();

#pragma unroll
        for (int k = 0; k < BK; k++) {
            float a[TM], b[TN];
#pragma unroll
            for (int i = 0; i < TM; i++) a[i] = As[k][ty * TM + i];
#pragma unroll
            for (int j = 0; j < TN; j++) b[j] = Bs[k][tx * TN + j];
#pragma unroll
            for (int i = 0; i < TM; i++)
#pragma unroll
                for (int j = 0; j < TN; j++) acc[i][j] = fmaf(a[i], b[j], acc[i][j]);
        }
        __syncthreads();
    }

#pragma unroll
    for (int i = 0; i < TM; i++) {
        int r = rowBase + ty * TM + i;
#pragma unroll
        for (int j = 0; j < TN; j++) {
            int n = tx * TN + j;
            g_kv[(size_t)r * (2 * DS) + n] = acc[i][j];
        }
    }
}

// wkv = exp(-exp(tf) * sigmoid(k)) * v
__global__ __launch_bounds__(256) void k_wkv() {
    int idx = blockIdx.x * 256 + threadIdx.x;
    if (idx >= ROWS * DS) return;
    int r = idx / DS, d = idx - r * DS;
    float kk = g_kv[(size_t)r * (2 * DS) + d];
    float vv = g_kv[(size_t)r * (2 * DS) + DS + d];
    float sg = 1.0f / (1.0f + expf(-kk));
    g_wkv[idx] = expf(-g_etf[d] * sg) * vv;
}

// per-chunk scan: h = h*w + wkv, h reset to 0 at each chunk start
__global__ __launch_bounds__(64) void k_scan() {
    int chunk = blockIdx.x;     // 0 .. Bn*NCHUNK-1
    int d = threadIdx.x;
    size_t base = (size_t)chunk * CHUNKL * DS + d;
    float w = g_w[d];
    float h = 0.0f;
#pragma unroll 4
    for (int t = 0; t < CHUNKL; t++) {
        h = fmaf(h, w, g_wkv[base + (size_t)t * DS]);
        g_hs[base + (size_t)t * DS] = h;
    }
}

// GEMM3: out = hs @ Wo   (K = 64)
__global__ __launch_bounds__(256) void k_gemm3(const float* __restrict__ Wo,
                                               float* __restrict__ out) {
    __shared__ float As[BK][BM];
    __shared__ float Bs[BK][BN];

    int tid = threadIdx.x;
    int rowBase = blockIdx.y * BM;
    int nBase   = blockIdx.x * BN;
    int ty = tid >> 4, tx = tid & 15;

    int arow = tid >> 1;
    int acol = (tid & 1) * 4;
    int brow = tid >> 5;
    int bcol = (tid & 31) * 4;

    float acc[TM][TN];
#pragma unroll
    for (int i = 0; i < TM; i++)
#pragma unroll
        for (int j = 0; j < TN; j++) acc[i][j] = 0.0f;

    const float* Aptr = g_hs + (size_t)(rowBase + arow) * DS;

    for (int kb = 0; kb < DS; kb += BK) {
        float4 av = *reinterpret_cast<const float4*>(Aptr + kb + acol);
        As[acol + 0][arow] = av.x;
        As[acol + 1][arow] = av.y;
        As[acol + 2][arow] = av.z;
        As[acol + 3][arow] = av.w;
        float4 bv = *reinterpret_cast<const float4*>(Wo + (size_t)(kb + brow) * DA + nBase + bcol);
        *reinterpret_cast<float4*>(&Bs[brow][bcol]) = bv;
        __syncthreads();

#pragma unroll
        for (int k = 0; k < BK; k++) {
            float a[TM], b[TN];
#pragma unroll
            for (int i = 0; i < TM; i++) a[i] = As[k][ty * TM + i];
#pragma unroll
            for (int j = 0; j < TN; j++) b[j] = Bs[k][tx * TN + j];
#pragma unroll
            for (int i = 0; i < TM; i++)
#pragma unroll
                for (int j = 0; j < TN; j++) acc[i][j] = fmaf(a[i], b[j], acc[i][j]);
        }
        __syncthreads();
    }

#pragma unroll
    for (int i = 0; i < TM; i++) {
        int r = rowBase + ty * TM + i;
#pragma unroll
        for (int j = 0; j < TN; j++) {
            int n = nBase + tx * TN + j;
            out[(size_t)r * DA + n] = acc[i][j];
        }
    }
}

// last_state[b,d] = sum_t coef2[63 - t/128, d] * coef[127 - t%128, d] * wkv[b,t,d]
__global__ __launch_bounds__(256) void k_last(float* __restrict__ ls) {
    int b  = blockIdx.x;
    int tg = threadIdx.x >> 6;   // 0..3
    int d  = threadIdx.x & 63;
    float acc = 0.0f;
    const float* wb = g_wkv + (size_t)b * Tn * DS;
    for (int t = tg; t < Tn; t += 4) {
        int c = t >> 7, j = t & 127;
        float kk = g_coef2[(NCHUNK - 1 - c) * DS + d] * g_coef[(CHUNKL - 1 - j) * DS + d];
        acc = fmaf(kk, wb[(size_t)t * DS + d], acc);
    }
    __shared__ float red[4][64];
    red[tg][d] = acc;
    __syncthreads();
    if (tg == 0)
        ls[b * DS + d] = red[0][d] + red[1][d] + red[2][d] + red[3][d];
}

// ---------------- launch ----------------
extern "C" void kernel_launch(void* const* d_in, const int* in_sizes, int n_in,
                              void* d_out, int out_size) {
    const float* x   = (const float*)d_in[0];
    const float* td  = (const float*)d_in[1];
    const float* tf  = (const float*)d_in[2];
    const float* Wk  = (const float*)d_in[3];
    const float* Wv  = (const float*)d_in[4];
    const float* Wo  = (const float*)d_in[5];
    const float* Wsh = (const float*)d_in[6];
    const float* sg  = (const float*)d_in[7];
    const float* lng = (const float*)d_in[8];
    const float* lnb = (const float*)d_in[9];
    float* out = (float*)d_out;

    k_prep<<<1, 64>>>(td, tf);

    dim3 g1(DA / BN, ROWS / BM);
    k_gemm1<<<g1, 256>>>(x, Wsh, sg);

    k_lnstats<<<ROWS, 256>>>();

    dim3 g2(1, ROWS / BM);
    k_gemm2<<<g2, 256>>>(Wk, Wv, lng, lnb);

    k_wkv<<<(ROWS * DS + 255) / 256, 256>>>();

    k_scan<<<Bn * NCHUNK, 64>>>();

    dim3 g3(DA / BN, ROWS / BM);
    k_gemm3<<<g3, 256>>>(Wo, out);

    // second output (last_state) appended after the main tensor if present
    if (out_size >= ROWS * DA + Bn * DS) {
        k_last<<<Bn, 256>>>(out + (size_t)ROWS * DA);
    }
}

// round 5
// speedup vs baseline: 1.5316x; 1.5316x over previous
#include <cuda_runtime.h>
#include <cuda_bf16.h>
#include <math.h>
#include <stdint.h>

// Problem constants
#define Bn     4
#define Tn     8192
#define DA     1024
#define DS     64
#define CHUNKL 128
#define NCHUNK 64            // Tn / CHUNKL
#define ROWS   (Bn * Tn)     // 32768
#define LN_EPS 1e-5f

// ---------------- scratch (__device__ globals; no allocation) ----------------
__device__ float g_xshift[(size_t)ROWS * DA];   // 128 MB
__device__ float g_kv[(size_t)ROWS * 2 * DS];   // 16 MB  (k | v per row)
__device__ float g_wkv[(size_t)ROWS * DS];      // 8 MB
__device__ float g_hs[(size_t)ROWS * DS];       // 8 MB
__device__ float g_mu[ROWS];
__device__ float g_rstd[ROWS];
__device__ float g_w[DS];
__device__ float g_etf[DS];
__device__ float g_coef[CHUNKL * DS];
__device__ float g_coef2[NCHUNK * DS];
// bf16 split operands for GEMM1
__device__ __nv_bfloat16 g_xh[(size_t)ROWS * DA];   // 64 MB
__device__ __nv_bfloat16 g_xl[(size_t)ROWS * DA];   // 64 MB
__device__ __nv_bfloat16 g_wth[(size_t)DA * DA];    // Wshift^T hi [n][k]
__device__ __nv_bfloat16 g_wtl[(size_t)DA * DA];    // Wshift^T lo [n][k]

// ======================= PTX helpers =======================
__device__ __forceinline__ uint32_t smem_to_u32(const void* p) {
    uint32_t a;
    asm("{ .reg .u64 t; cvta.to.shared.u64 t, %1; cvt.u32.u64 %0, t; }" : "=r"(a) : "l"(p));
    return a;
}

#define CP_ASYNC16(dst, src) asm volatile("cp.async.cg.shared.global [%0], [%1], 16;" :: "r"(dst), "l"(src) : "memory")
#define CP_COMMIT()          asm volatile("cp.async.commit_group;" ::: "memory")
#define CP_WAIT1()           asm volatile("cp.async.wait_group 1;" ::: "memory")
#define CP_WAIT0()           asm volatile("cp.async.wait_group 0;" ::: "memory")

#define LDSM4(r, a) \
    asm volatile("ldmatrix.sync.aligned.m8n8.x4.shared.b16 {%0,%1,%2,%3}, [%4];" \
        : "=r"((r)[0]), "=r"((r)[1]), "=r"((r)[2]), "=r"((r)[3]) : "r"(a))

#define MMA_BF16(c, a, b0, b1) \
    asm volatile("mma.sync.aligned.m16n8k16.row.col.f32.bf16.bf16.f32 " \
        "{%0,%1,%2,%3}, {%4,%5,%6,%7}, {%8,%9}, {%0,%1,%2,%3};" \
        : "+f"((c)[0]), "+f"((c)[1]), "+f"((c)[2]), "+f"((c)[3]) \
        : "r"((a)[0]), "r"((a)[1]), "r"((a)[2]), "r"((a)[3]), "r"(b0), "r"(b1))

// ---------------- prep: w, exp(tf), stride-scan impulse responses -----------
__global__ void k_prep(const float* __restrict__ td, const float* __restrict__ tf) {
    int d = threadIdx.x;
    if (d >= DS) return;
    float w = expf(td[d]);
    g_w[d]   = w;
    g_etf[d] = expf(tf[d]);

    float c[CHUNKL];
    c[0] = 1.0f;
    for (int i = 1; i < CHUNKL; i++) c[i] = 0.0f;
    for (int s = 1; s < CHUNKL; s++)
        for (int i = CHUNKL - 1; i >= s; i--)
            c[i] += w * c[i - s];
    for (int i = 0; i < CHUNKL; i++) g_coef[i * DS + d] = c[i];

    float W = expf((float)CHUNKL * td[d]);
    float c2[NCHUNK];
    c2[0] = 1.0f;
    for (int i = 1; i < NCHUNK; i++) c2[i] = 0.0f;
    for (int s = 1; s < NCHUNK; s++)
        for (int i = NCHUNK - 1; i >= s; i--)
            c2[i] += W * c2[i - s];
    for (int i = 0; i < NCHUNK; i++) g_coef2[i * DS + d] = c2[i];
}

// ---------------- x -> bf16 hi/lo split ----------------
__global__ __launch_bounds__(256) void k_split(const float* __restrict__ x) {
    size_t idx = (size_t)blockIdx.x * 256 + threadIdx.x;   // float4 index
    float4 v = reinterpret_cast<const float4*>(x)[idx];
    __nv_bfloat16 h0 = __float2bfloat16(v.x), h1 = __float2bfloat16(v.y);
    __nv_bfloat16 h2 = __float2bfloat16(v.z), h3 = __float2bfloat16(v.w);
    __nv_bfloat16 l0 = __float2bfloat16(v.x - __bfloat162float(h0));
    __nv_bfloat16 l1 = __float2bfloat16(v.y - __bfloat162float(h1));
    __nv_bfloat16 l2 = __float2bfloat16(v.z - __bfloat162float(h2));
    __nv_bfloat16 l3 = __float2bfloat16(v.w - __bfloat162float(h3));
    __nv_bfloat162* xh2 = reinterpret_cast<__nv_bfloat162*>(g_xh);
    __nv_bfloat162* xl2 = reinterpret_cast<__nv_bfloat162*>(g_xl);
    __nv_bfloat162 a, b;
    a.x = h0; a.y = h1; b.x = h2; b.y = h3;
    xh2[idx * 2] = a; xh2[idx * 2 + 1] = b;
    a.x = l0; a.y = l1; b.x = l2; b.y = l3;
    xl2[idx * 2] = a; xl2[idx * 2 + 1] = b;
}

// ---------------- Wshift transpose + bf16 split: WT[n][k] ----------------
__global__ __launch_bounds__(256) void k_wsplit(const float* __restrict__ Wsh) {
    __shared__ float t[32][33];
    int k0 = blockIdx.y * 32, n0 = blockIdx.x * 32;
    int tx = threadIdx.x & 31, ty = threadIdx.x >> 5;   // 32 x 8
#pragma unroll
    for (int j = 0; j < 4; j++) {
        int row = ty + j * 8;
        t[row][tx] = Wsh[(size_t)(k0 + row) * DA + n0 + tx];
    }
    __syncthreads();
#pragma unroll
    for (int j = 0; j < 4; j++) {
        int row = ty + j * 8;                 // n-offset
        float v = t[tx][row];                 // Wsh[k0+tx][n0+row]
        __nv_bfloat16 h = __float2bfloat16(v);
        __nv_bfloat16 l = __float2bfloat16(v - __bfloat162float(h));
        size_t o = (size_t)(n0 + row) * DA + k0 + tx;
        g_wth[o] = h;
        g_wtl[o] = l;
    }
}

// ================= GEMM1: mma.sync bf16 3-term split =================
// D[128x128] = sum_K (Ah*Bh + Ah*Bl + Al*Bh); A = x_cat rows, B = Wshift^T rows.
#define ROWB   80                           // 32 bf16 + 8 pad = 80 bytes/row
#define TILEB  (128 * ROWB)                 // 10240
#define STAGEB (4 * TILEB)                  // 40960 (Ah, Al, Bh, Bl)
#define SMEM_MMA1 (2 * STAGEB)              // 81920, double buffered
#define KSTAGES 32                          // K=1024 / 32

__global__ __launch_bounds__(256, 2) void k_mma1(const float* __restrict__ x,
                                                 const float* __restrict__ sgate) {
    extern __shared__ char smraw[];
    uint32_t sb0 = smem_to_u32(smraw);
    int tid = threadIdx.x;
    int l = tid & 31, wid = tid >> 5;
    int wm = wid & 3;          // warp row (32 M-rows each)
    int wn = wid >> 2;         // warp col (64 N-cols each)
    int Mbase = blockIdx.y * 128;
    int Nbase = blockIdx.x * 128;

    float acc[2][8][4];
#pragma unroll
    for (int i = 0; i < 2; i++)
#pragma unroll
        for (int j = 0; j < 8; j++)
#pragma unroll
            for (int q = 0; q < 4; q++) acc[i][j][q] = 0.0f;

    // ldmatrix lane address components (byte offsets within a tile)
    uint32_t a_lane = (uint32_t)(((l & 7) + ((l >> 3) & 1) * 8) * ROWB + ((l >> 4) & 1) * 16);
    uint32_t b_lane = (uint32_t)(((l & 7) + ((l >> 4) & 1) * 8) * ROWB + ((l >> 3) & 1) * 16);

    // ---- stage loader ----
    auto load_stage = [&](int s) {
        uint32_t dst = sb0 + (uint32_t)(s & 1) * STAGEB;
        int kb = s * 32;
#pragma unroll
        for (int c = 0; c < 2; c++) {
            int ch = tid * 2 + c;          // 0..511
            int row = ch >> 2, seg = ch & 3;
            uint32_t off = (uint32_t)(row * ROWB + seg * 16);
            int ks = kb + seg * 8;
            int ar = (Mbase + row) ^ 4096;   // x_cat row remap
            CP_ASYNC16(dst + off,             (const char*)(g_xh + (size_t)ar * DA + ks));
            CP_ASYNC16(dst + TILEB + off,     (const char*)(g_xl + (size_t)ar * DA + ks));
            int br = Nbase + row;
            CP_ASYNC16(dst + 2 * TILEB + off, (const char*)(g_wth + (size_t)br * DA + ks));
            CP_ASYNC16(dst + 3 * TILEB + off, (const char*)(g_wtl + (size_t)br * DA + ks));
        }
        CP_COMMIT();
    };

    load_stage(0);
    for (int s = 0; s < KSTAGES; s++) {
        if (s + 1 < KSTAGES) { load_stage(s + 1); CP_WAIT1(); }
        else                 { CP_WAIT0(); }
        __syncthreads();

        uint32_t base = sb0 + (uint32_t)(s & 1) * STAGEB;
#pragma unroll
        for (int h = 0; h < 2; h++) {
            uint32_t kkB = (uint32_t)(h * 32);   // k16 half, bytes
            uint32_t ah_[2][4], al_[2][4];
#pragma unroll
            for (int i = 0; i < 2; i++) {
                uint32_t aaddr = base + (uint32_t)((wm * 32 + i * 16) * ROWB) + kkB + a_lane;
                LDSM4(ah_[i], aaddr);
                LDSM4(al_[i], aaddr + TILEB);
            }
#pragma unroll
            for (int p = 0; p < 4; p++) {
                uint32_t baddr = base + 2 * TILEB + (uint32_t)((wn * 64 + p * 16) * ROWB) + kkB + b_lane;
                uint32_t bh_[4], bl_[4];
                LDSM4(bh_, baddr);
                LDSM4(bl_, baddr + TILEB);
#pragma unroll
                for (int i = 0; i < 2; i++) {
                    MMA_BF16(acc[i][2 * p],     ah_[i], bh_[0], bh_[1]);
                    MMA_BF16(acc[i][2 * p],     ah_[i], bl_[0], bl_[1]);
                    MMA_BF16(acc[i][2 * p],     al_[i], bh_[0], bh_[1]);
                    MMA_BF16(acc[i][2 * p + 1], ah_[i], bh_[2], bh_[3]);
                    MMA_BF16(acc[i][2 * p + 1], ah_[i], bl_[2], bl_[3]);
                    MMA_BF16(acc[i][2 * p + 1], al_[i], bh_[2], bh_[3]);
                }
            }
        }
        __syncthreads();
    }

    // epilogue: gate mix, write g_xshift
    int g = l >> 2, tig = l & 3;
#pragma unroll
    for (int i = 0; i < 2; i++) {
        int r0 = Mbase + wm * 32 + i * 16 + g;
        int r1 = r0 + 8;
#pragma unroll
        for (int j = 0; j < 8; j++) {
            int cn = Nbase + wn * 64 + j * 8 + tig * 2;
            float g0 = 1.0f / (1.0f + expf(-sgate[cn]));
            float g1 = 1.0f / (1.0f + expf(-sgate[cn + 1]));
            size_t o00 = (size_t)r0 * DA + cn;
            size_t o10 = (size_t)r1 * DA + cn;
            g_xshift[o00]     = acc[i][j][0] * g0 + x[o00]     * (1.0f - g0);
            g_xshift[o00 + 1] = acc[i][j][1] * g1 + x[o00 + 1] * (1.0f - g1);
            g_xshift[o10]     = acc[i][j][2] * g0 + x[o10]     * (1.0f - g0);
            g_xshift[o10 + 1] = acc[i][j][3] * g1 + x[o10 + 1] * (1.0f - g1);
        }
    }
}

// ---------------- LayerNorm stats ----------------
__global__ __launch_bounds__(256) void k_lnstats() {
    int r = blockIdx.x;
    const float* xr = g_xshift + (size_t)r * DA;
    float s = 0.0f, s2 = 0.0f;
    for (int i = threadIdx.x; i < DA; i += 256) {
        float v = xr[i];
        s += v;
        s2 = fmaf(v, v, s2);
    }
#pragma unroll
    for (int o = 16; o > 0; o >>= 1) {
        s  += __shfl_down_sync(0xffffffffu, s, o);
        s2 += __shfl_down_sync(0xffffffffu, s2, o);
    }
    __shared__ float ss[8], ss2[8];
    int w = threadIdx.x >> 5;
    if ((threadIdx.x & 31) == 0) { ss[w] = s; ss2[w] = s2; }
    __syncthreads();
    if (threadIdx.x == 0) {
        float S = 0.0f, S2 = 0.0f;
#pragma unroll
        for (int i = 0; i < 8; i++) { S += ss[i]; S2 += ss2[i]; }
        float mu  = S / (float)DA;
        float var = S2 / (float)DA - mu * mu;
        g_mu[r]   = mu;
        g_rstd[r] = rsqrtf(var + LN_EPS);
    }
}

// ---------------- SIMT GEMM config (gemm2/gemm3) ----------------
#define BM 128
#define BN 128
#define BK 8
#define TM 8
#define TN 8

// GEMM2: [k|v] = layernorm(x_shift) @ [Wk|Wv]   (N = 128)
__global__ __launch_bounds__(256) void k_gemm2(const float* __restrict__ Wk,
                                               const float* __restrict__ Wv,
                                               const float* __restrict__ lng,
                                               const float* __restrict__ lnb) {
    __shared__ float As[BK][BM];
    __shared__ float Bs[BK][BN];

    int tid = threadIdx.x;
    int rowBase = blockIdx.y * BM;
    int ty = tid >> 4, tx = tid & 15;

    int arow = tid >> 1;
    int acol = (tid & 1) * 4;
    int brow = tid >> 5;
    int bcol = (tid & 31) * 4;

    float acc[TM][TN];
#pragma unroll
    for (int i = 0; i < TM; i++)
#pragma unroll
        for (int j = 0; j < TN; j++) acc[i][j] = 0.0f;

    int gr = rowBase + arow;
    float mu = g_mu[gr], rstd = g_rstd[gr];
    const float* Aptr = g_xshift + (size_t)gr * DA;

    for (int kb = 0; kb < DA; kb += BK) {
        float4 av = *reinterpret_cast<const float4*>(Aptr + kb + acol);
        float4 gv = *reinterpret_cast<const float4*>(lng + kb + acol);
        float4 bvv = *reinterpret_cast<const float4*>(lnb + kb + acol);
        As[acol + 0][arow] = (av.x - mu) * rstd * gv.x + bvv.x;
        As[acol + 1][arow] = (av.y - mu) * rstd * gv.y + bvv.y;
        As[acol + 2][arow] = (av.z - mu) * rstd * gv.z + bvv.z;
        As[acol + 3][arow] = (av.w - mu) * rstd * gv.w + bvv.w;
        float4 bv;
        if (bcol < DS)
            bv = *reinterpret_cast<const float4*>(Wk + (size_t)(kb + brow) * DS + bcol);
        else
            bv = *reinterpret_cast<const float4*>(Wv + (size_t)(kb + brow) * DS + (bcol - DS));
        *reinterpret_cast<float4*>(&Bs[brow][bcol]) = bv;
        __syncthreads();

#pragma unroll
        for (int k = 0; k < BK; k++) {
            float a[TM], b[TN];
#pragma unroll
            for (int i = 0; i < TM; i++) a[i] = As[k][ty * TM + i];
#pragma unroll
            for (int j = 0; j < TN; j++) b[j] = Bs[k][tx * TN + j];
#pragma unroll
            for (int i = 0; i < TM; i++)
#pragma unroll
                for (int j = 0; j < TN; j++) acc[i][j] = fmaf(a[i], b[j], acc[i][j]);
        }
        __syncthreads();
    }

#pragma unroll
    for (int i = 0; i < TM; i++) {
        int r = rowBase + ty * TM + i;
#pragma unroll
        for (int j = 0; j < TN; j++) {
            int n = tx * TN + j;
            g_kv[(size_t)r * (2 * DS) + n] = acc[i][j];
        }
    }
}

// wkv = exp(-exp(tf) * sigmoid(k)) * v
__global__ __launch_bounds__(256) void k_wkv() {
    int idx = blockIdx.x * 256 + threadIdx.x;
    if (idx >= ROWS * DS) return;
    int r = idx / DS, d = idx - r * DS;
    float kk = g_kv[(size_t)r * (2 * DS) + d];
    float vv = g_kv[(size_t)r * (2 * DS) + DS + d];
    float sg = 1.0f / (1.0f + expf(-kk));
    g_wkv[idx] = expf(-g_etf[d] * sg) * vv;
}

// per-chunk scan
__global__ __launch_bounds__(64) void k_scan() {
    int chunk = blockIdx.x;
    int d = threadIdx.x;
    size_t base = (size_t)chunk * CHUNKL * DS + d;
    float w = g_w[d];
    float h = 0.0f;
#pragma unroll 4
    for (int t = 0; t < CHUNKL; t++) {
        h = fmaf(h, w, g_wkv[base + (size_t)t * DS]);
        g_hs[base + (size_t)t * DS] = h;
    }
}

// GEMM3: out = hs @ Wo   (K = 64)
__global__ __launch_bounds__(256) void k_gemm3(const float* __restrict__ Wo,
                                               float* __restrict__ out) {
    __shared__ float As[BK][BM];
    __shared__ float Bs[BK][BN];

    int tid = threadIdx.x;
    int rowBase = blockIdx.y * BM;
    int nBase   = blockIdx.x * BN;
    int ty = tid >> 4, tx = tid & 15;

    int arow = tid >> 1;
    int acol = (tid & 1) * 4;
    int brow = tid >> 5;
    int bcol = (tid & 31) * 4;

    float acc[TM][TN];
#pragma unroll
    for (int i = 0; i < TM; i++)
#pragma unroll
        for (int j = 0; j < TN; j++) acc[i][j] = 0.0f;

    const float* Aptr = g_hs + (size_t)(rowBase + arow) * DS;

    for (int kb = 0; kb < DS; kb += BK) {
        float4 av = *reinterpret_cast<const float4*>(Aptr + kb + acol);
        As[acol + 0][arow] = av.x;
        As[acol + 1][arow] = av.y;
        As[acol + 2][arow] = av.z;
        As[acol + 3][arow] = av.w;
        float4 bv = *reinterpret_cast<const float4*>(Wo + (size_t)(kb + brow) * DA + nBase + bcol);
        *reinterpret_cast<float4*>(&Bs[brow][bcol]) = bv;
        __syncthreads();

#pragma unroll
        for (int k = 0; k < BK; k++) {
            float a[TM], b[TN];
#pragma unroll
            for (int i = 0; i < TM; i++) a[i] = As[k][ty * TM + i];
#pragma unroll
            for (int j = 0; j < TN; j++) b[j] = Bs[k][tx * TN + j];
#pragma unroll
            for (int i = 0; i < TM; i++)
#pragma unroll
                for (int j = 0; j < TN; j++) acc[i][j] = fmaf(a[i], b[j], acc[i][j]);
        }
        __syncthreads();
    }

#pragma unroll
    for (int i = 0; i < TM; i++) {
        int r = rowBase + ty * TM + i;
#pragma unroll
        for (int j = 0; j < TN; j++) {
            int n = nBase + tx * TN + j;
            out[(size_t)r * DA + n] = acc[i][j];
        }
    }
}

// last_state
__global__ __launch_bounds__(256) void k_last(float* __restrict__ ls) {
    int b  = blockIdx.x;
    int tg = threadIdx.x >> 6;
    int d  = threadIdx.x & 63;
    float acc = 0.0f;
    const float* wb = g_wkv + (size_t)b * Tn * DS;
    for (int t = tg; t < Tn; t += 4) {
        int c = t >> 7, j = t & 127;
        float kk = g_coef2[(NCHUNK - 1 - c) * DS + d] * g_coef[(CHUNKL - 1 - j) * DS + d];
        acc = fmaf(kk, wb[(size_t)t * DS + d], acc);
    }
    __shared__ float red[4][64];
    red[tg][d] = acc;
    __syncthreads();
    if (tg == 0)
        ls[b * DS + d] = red[0][d] + red[1][d] + red[2][d] + red[3][d];
}

// ---------------- launch ----------------
extern "C" void kernel_launch(void* const* d_in, const int* in_sizes, int n_in,
                              void* d_out, int out_size) {
    const float* x   = (const float*)d_in[0];
    const float* td  = (const float*)d_in[1];
    const float* tf  = (const float*)d_in[2];
    const float* Wk  = (const float*)d_in[3];
    const float* Wv  = (const float*)d_in[4];
    const float* Wo  = (const float*)d_in[5];
    const float* Wsh = (const float*)d_in[6];
    const float* sg  = (const float*)d_in[7];
    const float* lng = (const float*)d_in[8];
    const float* lnb = (const float*)d_in[9];
    float* out = (float*)d_out;

    static int smem_set = 0;
    if (!smem_set) {
        cudaFuncSetAttribute(k_mma1, cudaFuncAttributeMaxDynamicSharedMemorySize, SMEM_MMA1);
        smem_set = 1;
    }

    k_prep<<<1, 64>>>(td, tf);
    k_split<<<(int)((size_t)ROWS * DA / 4 / 256), 256>>>(x);
    {
        dim3 gw(DA / 32, DA / 32);
        k_wsplit<<<gw, 256>>>(Wsh);
    }
    {
        dim3 g1(DA / 128, ROWS / 128);
        k_mma1<<<g1, 256, SMEM_MMA1>>>(x, sg);
    }
    k_lnstats<<<ROWS, 256>>>();
    {
        dim3 g2(1, ROWS / BM);
        k_gemm2<<<g2, 256>>>(Wk, Wv, lng, lnb);
    }
    k_wkv<<<(ROWS * DS + 255) / 256, 256>>>();
    k_scan<<<Bn * NCHUNK, 64>>>();
    {
        dim3 g3(DA / BN, ROWS / BM);
        k_gemm3<<<g3, 256>>>(Wo, out);
    }
    if (out_size >= ROWS * DA + Bn * DS) {
        k_last<<<Bn, 256>>>(out + (size_t)ROWS * DA);
    }
}

// round 6
// speedup vs baseline: 1.9431x; 1.2686x over previous
#include <cuda_runtime.h>
#include <cuda_bf16.h>
#include <math.h>
#include <stdint.h>

// Problem constants
#define Bn     4
#define Tn     8192
#define DA     1024
#define DS     64
#define CHUNKL 128
#define NCHUNK 64            // Tn / CHUNKL
#define ROWS   (Bn * Tn)     // 32768
#define LN_EPS 1e-5f

// ---------------- scratch (__device__ globals; no allocation) ----------------
__device__ float g_kv[(size_t)ROWS * 2 * DS];   // 16 MB  (k | v per row)
__device__ float g_wkv[(size_t)ROWS * DS];      // 8 MB
__device__ float g_mu[ROWS];
__device__ float g_rstd[ROWS];
__device__ float g_w[DS];
__device__ float g_etf[DS];
__device__ float g_coef[CHUNKL * DS];
__device__ float g_coef2[NCHUNK * DS];
__device__ float g_c1[2 * DS];                  // lng @ [Wk|Wv]
__device__ float g_c0[2 * DS];                  // lnb @ [Wk|Wv]
__device__ float g_psum[16 * ROWS];             // partial row sums of x_shift
__device__ float g_psum2[16 * ROWS];            // partial row sums of x_shift^2
// bf16 split operands
__device__ __nv_bfloat16 g_xh[(size_t)ROWS * DA];   // x hi
__device__ __nv_bfloat16 g_xl[(size_t)ROWS * DA];   // x lo
__device__ __nv_bfloat16 g_uh[(size_t)ROWS * DA];   // u = x_shift*lng hi
__device__ __nv_bfloat16 g_ul[(size_t)ROWS * DA];   // u lo
__device__ __nv_bfloat16 g_wth[(size_t)DA * DA];    // Wshift^T hi [n][k]
__device__ __nv_bfloat16 g_wtl[(size_t)DA * DA];    // Wshift^T lo
__device__ __nv_bfloat16 g_w2th[(size_t)128 * DA];  // [Wk|Wv]^T hi [n][k]
__device__ __nv_bfloat16 g_w2tl[(size_t)128 * DA];
__device__ __nv_bfloat16 g_woth[(size_t)DA * DS];   // Wo^T hi [n][k]
__device__ __nv_bfloat16 g_wotl[(size_t)DA * DS];
__device__ __nv_bfloat16 g_hsh[(size_t)ROWS * DS];  // hs hi
__device__ __nv_bfloat16 g_hsl[(size_t)ROWS * DS];  // hs lo

// ======================= PTX helpers =======================
__device__ __forceinline__ uint32_t smem_to_u32(const void* p) {
    uint32_t a;
    asm("{ .reg .u64 t; cvta.to.shared.u64 t, %1; cvt.u32.u64 %0, t; }" : "=r"(a) : "l"(p));
    return a;
}

#define CP_ASYNC16(dst, src) asm volatile("cp.async.cg.shared.global [%0], [%1], 16;" :: "r"(dst), "l"(src) : "memory")
#define CP_COMMIT()          asm volatile("cp.async.commit_group;" ::: "memory")
#define CP_WAIT0()           asm volatile("cp.async.wait_group 0;" ::: "memory")

#define LDSM4(r, a) \
    asm volatile("ldmatrix.sync.aligned.m8n8.x4.shared.b16 {%0,%1,%2,%3}, [%4];" \
        : "=r"((r)[0]), "=r"((r)[1]), "=r"((r)[2]), "=r"((r)[3]) : "r"(a))

#define MMA_BF16(c, a, b0, b1) \
    asm volatile("mma.sync.aligned.m16n8k16.row.col.f32.bf16.bf16.f32 " \
        "{%0,%1,%2,%3}, {%4,%5,%6,%7}, {%8,%9}, {%0,%1,%2,%3};" \
        : "+f"((c)[0]), "+f"((c)[1]), "+f"((c)[2]), "+f"((c)[3]) \
        : "r"((a)[0]), "r"((a)[1]), "r"((a)[2]), "r"((a)[3]), "r"(b0), "r"(b1))

__device__ __forceinline__ float sigm(float v) { return 1.0f / (1.0f + expf(-v)); }

// ---------------- prep ----------------
__global__ void k_prep(const float* __restrict__ td, const float* __restrict__ tf) {
    int d = threadIdx.x;
    if (d >= DS) return;
    float w = expf(td[d]);
    g_w[d]   = w;
    g_etf[d] = expf(tf[d]);

    float c[CHUNKL];
    c[0] = 1.0f;
    for (int i = 1; i < CHUNKL; i++) c[i] = 0.0f;
    for (int s = 1; s < CHUNKL; s++)
        for (int i = CHUNKL - 1; i >= s; i--)
            c[i] += w * c[i - s];
    for (int i = 0; i < CHUNKL; i++) g_coef[i * DS + d] = c[i];

    float W = expf((float)CHUNKL * td[d]);
    float c2[NCHUNK];
    c2[0] = 1.0f;
    for (int i = 1; i < NCHUNK; i++) c2[i] = 0.0f;
    for (int s = 1; s < NCHUNK; s++)
        for (int i = NCHUNK - 1; i >= s; i--)
            c2[i] += W * c2[i - s];
    for (int i = 0; i < NCHUNK; i++) g_coef2[i * DS + d] = c2[i];
}

// ---------------- x -> bf16 hi/lo split ----------------
__global__ __launch_bounds__(256) void k_split(const float* __restrict__ x) {
    size_t idx = (size_t)blockIdx.x * 256 + threadIdx.x;   // float4 index
    float4 v = reinterpret_cast<const float4*>(x)[idx];
    __nv_bfloat16 h0 = __float2bfloat16(v.x), h1 = __float2bfloat16(v.y);
    __nv_bfloat16 h2 = __float2bfloat16(v.z), h3 = __float2bfloat16(v.w);
    __nv_bfloat162* xh2 = reinterpret_cast<__nv_bfloat162*>(g_xh);
    __nv_bfloat162* xl2 = reinterpret_cast<__nv_bfloat162*>(g_xl);
    __nv_bfloat162 a, b;
    a.x = h0; a.y = h1; b.x = h2; b.y = h3;
    xh2[idx * 2] = a; xh2[idx * 2 + 1] = b;
    a.x = __float2bfloat16(v.x - __bfloat162float(h0));
    a.y = __float2bfloat16(v.y - __bfloat162float(h1));
    b.x = __float2bfloat16(v.z - __bfloat162float(h2));
    b.y = __float2bfloat16(v.w - __bfloat162float(h3));
    xl2[idx * 2] = a; xl2[idx * 2 + 1] = b;
}

// ---------------- Wshift transpose + bf16 split: WT[n][k] ----------------
__global__ __launch_bounds__(256) void k_wsplit(const float* __restrict__ Wsh) {
    __shared__ float t[32][33];
    int k0 = blockIdx.y * 32, n0 = blockIdx.x * 32;
    int tx = threadIdx.x & 31, ty = threadIdx.x >> 5;   // 32 x 8
#pragma unroll
    for (int j = 0; j < 4; j++) {
        int row = ty + j * 8;
        t[row][tx] = Wsh[(size_t)(k0 + row) * DA + n0 + tx];
    }
    __syncthreads();
#pragma unroll
    for (int j = 0; j < 4; j++) {
        int row = ty + j * 8;                 // n-offset
        float v = t[tx][row];
        __nv_bfloat16 h = __float2bfloat16(v);
        __nv_bfloat16 l = __float2bfloat16(v - __bfloat162float(h));
        size_t o = (size_t)(n0 + row) * DA + k0 + tx;
        g_wth[o] = h;
        g_wtl[o] = l;
    }
}

// ---------------- [Wk|Wv]^T split: W2T[n][k], n<64 -> Wk, n>=64 -> Wv -------
__global__ __launch_bounds__(256) void k_w2split(const float* __restrict__ Wk,
                                                 const float* __restrict__ Wv) {
    int idx = blockIdx.x * 256 + threadIdx.x;    // 128*1024
    int n = idx >> 10, k = idx & 1023;
    float v = (n < DS) ? Wk[(size_t)k * DS + n] : Wv[(size_t)k * DS + (n - DS)];
    __nv_bfloat16 h = __float2bfloat16(v);
    g_w2th[idx] = h;
    g_w2tl[idx] = __float2bfloat16(v - __bfloat162float(h));
}

// ---------------- Wo^T split: WoT[n][k] = Wo[k][n] ----------------
__global__ __launch_bounds__(256) void k_wosplit(const float* __restrict__ Wo) {
    int idx = blockIdx.x * 256 + threadIdx.x;    // 1024*64
    int n = idx >> 6, k = idx & 63;
    float v = Wo[(size_t)k * DA + n];
    __nv_bfloat16 h = __float2bfloat16(v);
    g_woth[idx] = h;
    g_wotl[idx] = __float2bfloat16(v - __bfloat162float(h));
}

// ---------------- c1 = lng @ [Wk|Wv], c0 = lnb @ [Wk|Wv] ----------------
__global__ __launch_bounds__(256) void k_cvec(const float* __restrict__ Wk,
                                              const float* __restrict__ Wv,
                                              const float* __restrict__ lng,
                                              const float* __restrict__ lnb) {
    int n = blockIdx.x;                           // 0..127
    const float* W = (n < DS) ? Wk : Wv;
    int col = (n < DS) ? n : n - DS;
    float s1 = 0.0f, s0 = 0.0f;
    for (int k = threadIdx.x; k < DA; k += 256) {
        float w = W[(size_t)k * DS + col];
        s1 = fmaf(lng[k], w, s1);
        s0 = fmaf(lnb[k], w, s0);
    }
#pragma unroll
    for (int o = 16; o > 0; o >>= 1) {
        s1 += __shfl_down_sync(0xffffffffu, s1, o);
        s0 += __shfl_down_sync(0xffffffffu, s0, o);
    }
    __shared__ float a1[8], a0[8];
    int w = threadIdx.x >> 5;
    if ((threadIdx.x & 31) == 0) { a1[w] = s1; a0[w] = s0; }
    __syncthreads();
    if (threadIdx.x == 0) {
        float S1 = 0.0f, S0 = 0.0f;
#pragma unroll
        for (int i = 0; i < 8; i++) { S1 += a1[i]; S0 += a0[i]; }
        g_c1[n] = S1;
        g_c0[n] = S0;
    }
}

// ================= GEMM1: mma.sync bf16 3-term split =================
#define ROWB   80                           // 32 bf16 + 8 pad = 80 bytes/row
#define TILEB  (128 * ROWB)                 // 10240
#define STAGEB (4 * TILEB)                  // 40960 (Ah, Al, Bh, Bl)
#define SMEM_MMA1 (2 * STAGEB)              // 81920, double buffered
#define KSTAGES 32                          // K=1024 / 32

__global__ __launch_bounds__(256, 2) void k_mma1(const float* __restrict__ x,
                                                 const float* __restrict__ sgate,
                                                 const float* __restrict__ lng) {
    extern __shared__ char smraw[];
    uint32_t sb0 = smem_to_u32(smraw);
    int tid = threadIdx.x;
    int l = tid & 31, wid = tid >> 5;
    int wm = wid & 3;          // warp row (32 M-rows each)
    int wn = wid >> 2;         // warp col (64 N-cols each)
    int Mbase = blockIdx.y * 128;
    int Nbase = blockIdx.x * 128;

    float acc[2][8][4];
#pragma unroll
    for (int i = 0; i < 2; i++)
#pragma unroll
        for (int j = 0; j < 8; j++)
#pragma unroll
            for (int q = 0; q < 4; q++) acc[i][j][q] = 0.0f;

    uint32_t a_lane = (uint32_t)(((l & 7) + ((l >> 3) & 1) * 8) * ROWB + ((l >> 4) & 1) * 16);
    uint32_t b_lane = (uint32_t)(((l & 7) + ((l >> 4) & 1) * 8) * ROWB + ((l >> 3) & 1) * 16);

    auto load_stage = [&](int s) {
        uint32_t dst = sb0 + (uint32_t)(s & 1) * STAGEB;
        int kb = s * 32;
#pragma unroll
        for (int c = 0; c < 2; c++) {
            int ch = tid * 2 + c;
            int row = ch >> 2, seg = ch & 3;
            uint32_t off = (uint32_t)(row * ROWB + seg * 16);
            int ks = kb + seg * 8;
            int ar = (Mbase + row) ^ 4096;
            CP_ASYNC16(dst + off,             (const char*)(g_xh + (size_t)ar * DA + ks));
            CP_ASYNC16(dst + TILEB + off,     (const char*)(g_xl + (size_t)ar * DA + ks));
            int br = Nbase + row;
            CP_ASYNC16(dst + 2 * TILEB + off, (const char*)(g_wth + (size_t)br * DA + ks));
            CP_ASYNC16(dst + 3 * TILEB + off, (const char*)(g_wtl + (size_t)br * DA + ks));
        }
        CP_COMMIT();
    };

    load_stage(0);
    for (int s = 0; s < KSTAGES; s++) {
        CP_WAIT0();
        __syncthreads();
        if (s + 1 < KSTAGES) load_stage(s + 1);

        uint32_t base = sb0 + (uint32_t)(s & 1) * STAGEB;
#pragma unroll
        for (int h = 0; h < 2; h++) {
            uint32_t kkB = (uint32_t)(h * 32);
            uint32_t ah_[2][4], al_[2][4];
#pragma unroll
            for (int i = 0; i < 2; i++) {
                uint32_t aaddr = base + (uint32_t)((wm * 32 + i * 16) * ROWB) + kkB + a_lane;
                LDSM4(ah_[i], aaddr);
                LDSM4(al_[i], aaddr + TILEB);
            }
#pragma unroll
            for (int p = 0; p < 4; p++) {
                uint32_t baddr = base + 2 * TILEB + (uint32_t)((wn * 64 + p * 16) * ROWB) + kkB + b_lane;
                uint32_t bh_[4], bl_[4];
                LDSM4(bh_, baddr);
                LDSM4(bl_, baddr + TILEB);
#pragma unroll
                for (int i = 0; i < 2; i++) {
                    MMA_BF16(acc[i][2 * p],     ah_[i], bh_[0], bh_[1]);
                    MMA_BF16(acc[i][2 * p],     ah_[i], bl_[0], bl_[1]);
                    MMA_BF16(acc[i][2 * p],     al_[i], bh_[0], bh_[1]);
                    MMA_BF16(acc[i][2 * p + 1], ah_[i], bh_[2], bh_[3]);
                    MMA_BF16(acc[i][2 * p + 1], ah_[i], bl_[2], bl_[3]);
                    MMA_BF16(acc[i][2 * p + 1], al_[i], bh_[2], bh_[3]);
                }
            }
        }
    }

    // epilogue: gate mix, write u = x_shift*lng as bf16 split, partial LN sums
    int g = l >> 2, tig = l & 3;
    int cb = blockIdx.x * 2 + wn;           // 0..15 partial-sum slot
#pragma unroll
    for (int i = 0; i < 2; i++) {
        int r0 = Mbase + wm * 32 + i * 16 + g;
        int r1 = r0 + 8;
        float rs0 = 0.0f, rq0 = 0.0f, rs1 = 0.0f, rq1 = 0.0f;
#pragma unroll
        for (int j = 0; j < 8; j++) {
            int cn = Nbase + wn * 64 + j * 8 + tig * 2;
            float g0 = sigm(sgate[cn]);
            float g1 = sigm(sgate[cn + 1]);
            size_t o00 = (size_t)r0 * DA + cn;
            size_t o10 = (size_t)r1 * DA + cn;
            float xs00 = acc[i][j][0] * g0 + x[o00]     * (1.0f - g0);
            float xs01 = acc[i][j][1] * g1 + x[o00 + 1] * (1.0f - g1);
            float xs10 = acc[i][j][2] * g0 + x[o10]     * (1.0f - g0);
            float xs11 = acc[i][j][3] * g1 + x[o10 + 1] * (1.0f - g1);
            rs0 += xs00 + xs01;  rq0 += xs00 * xs00 + xs01 * xs01;
            rs1 += xs10 + xs11;  rq1 += xs10 * xs10 + xs11 * xs11;
            float ln0 = lng[cn], ln1 = lng[cn + 1];
            float u00 = xs00 * ln0, u01 = xs01 * ln1;
            float u10 = xs10 * ln0, u11 = xs11 * ln1;
            __nv_bfloat162 hh, ll;
            hh.x = __float2bfloat16(u00); hh.y = __float2bfloat16(u01);
            ll.x = __float2bfloat16(u00 - __bfloat162float(hh.x));
            ll.y = __float2bfloat16(u01 - __bfloat162float(hh.y));
            *reinterpret_cast<__nv_bfloat162*>(g_uh + o00) = hh;
            *reinterpret_cast<__nv_bfloat162*>(g_ul + o00) = ll;
            hh.x = __float2bfloat16(u10); hh.y = __float2bfloat16(u11);
            ll.x = __float2bfloat16(u10 - __bfloat162float(hh.x));
            ll.y = __float2bfloat16(u11 - __bfloat162float(hh.y));
            *reinterpret_cast<__nv_bfloat162*>(g_uh + o10) = hh;
            *reinterpret_cast<__nv_bfloat162*>(g_ul + o10) = ll;
        }
        // reduce across the 4-lane quad (tig)
        rs0 += __shfl_xor_sync(0xffffffffu, rs0, 1); rs0 += __shfl_xor_sync(0xffffffffu, rs0, 2);
        rq0 += __shfl_xor_sync(0xffffffffu, rq0, 1); rq0 += __shfl_xor_sync(0xffffffffu, rq0, 2);
        rs1 += __shfl_xor_sync(0xffffffffu, rs1, 1); rs1 += __shfl_xor_sync(0xffffffffu, rs1, 2);
        rq1 += __shfl_xor_sync(0xffffffffu, rq1, 1); rq1 += __shfl_xor_sync(0xffffffffu, rq1, 2);
        if (tig == 0) {
            g_psum [cb * ROWS + r0] = rs0;
            g_psum2[cb * ROWS + r0] = rq0;
            g_psum [cb * ROWS + r1] = rs1;
            g_psum2[cb * ROWS + r1] = rq1;
        }
    }
}

// ---------------- LN finalize ----------------
__global__ __launch_bounds__(256) void k_lnfin() {
    int r = blockIdx.x * 256 + threadIdx.x;
    float s = 0.0f, s2 = 0.0f;
#pragma unroll
    for (int cb = 0; cb < 16; cb++) {
        s  += g_psum [cb * ROWS + r];
        s2 += g_psum2[cb * ROWS + r];
    }
    float mu  = s * (1.0f / (float)DA);
    float var = s2 * (1.0f / (float)DA) - mu * mu;
    g_mu[r]   = mu;
    g_rstd[r] = rsqrtf(var + LN_EPS);
}

// ================= GEMM2: [k|v] = u @ W2T with affine LN correction ========
__global__ __launch_bounds__(256, 2) void k_mma2() {
    extern __shared__ char smraw[];
    uint32_t sb0 = smem_to_u32(smraw);
    int tid = threadIdx.x;
    int l = tid & 31, wid = tid >> 5;
    int wm = wid & 3;
    int wn = wid >> 2;
    int Mbase = blockIdx.y * 128;

    float acc[2][8][4];
#pragma unroll
    for (int i = 0; i < 2; i++)
#pragma unroll
        for (int j = 0; j < 8; j++)
#pragma unroll
            for (int q = 0; q < 4; q++) acc[i][j][q] = 0.0f;

    uint32_t a_lane = (uint32_t)(((l & 7) + ((l >> 3) & 1) * 8) * ROWB + ((l >> 4) & 1) * 16);
    uint32_t b_lane = (uint32_t)(((l & 7) + ((l >> 4) & 1) * 8) * ROWB + ((l >> 3) & 1) * 16);

    auto load_stage = [&](int s) {
        uint32_t dst = sb0 + (uint32_t)(s & 1) * STAGEB;
        int kb = s * 32;
#pragma unroll
        for (int c = 0; c < 2; c++) {
            int ch = tid * 2 + c;
            int row = ch >> 2, seg = ch & 3;
            uint32_t off = (uint32_t)(row * ROWB + seg * 16);
            int ks = kb + seg * 8;
            int ar = Mbase + row;
            CP_ASYNC16(dst + off,             (const char*)(g_uh + (size_t)ar * DA + ks));
            CP_ASYNC16(dst + TILEB + off,     (const char*)(g_ul + (size_t)ar * DA + ks));
            CP_ASYNC16(dst + 2 * TILEB + off, (const char*)(g_w2th + (size_t)row * DA + ks));
            CP_ASYNC16(dst + 3 * TILEB + off, (const char*)(g_w2tl + (size_t)row * DA + ks));
        }
        CP_COMMIT();
    };

    load_stage(0);
    for (int s = 0; s < KSTAGES; s++) {
        CP_WAIT0();
        __syncthreads();
        if (s + 1 < KSTAGES) load_stage(s + 1);

        uint32_t base = sb0 + (uint32_t)(s & 1) * STAGEB;
#pragma unroll
        for (int h = 0; h < 2; h++) {
            uint32_t kkB = (uint32_t)(h * 32);
            uint32_t ah_[2][4], al_[2][4];
#pragma unroll
            for (int i = 0; i < 2; i++) {
                uint32_t aaddr = base + (uint32_t)((wm * 32 + i * 16) * ROWB) + kkB + a_lane;
                LDSM4(ah_[i], aaddr);
                LDSM4(al_[i], aaddr + TILEB);
            }
#pragma unroll
            for (int p = 0; p < 4; p++) {
                uint32_t baddr = base + 2 * TILEB + (uint32_t)((wn * 64 + p * 16) * ROWB) + kkB + b_lane;
                uint32_t bh_[4], bl_[4];
                LDSM4(bh_, baddr);
                LDSM4(bl_, baddr + TILEB);
#pragma unroll
                for (int i = 0; i < 2; i++) {
                    MMA_BF16(acc[i][2 * p],     ah_[i], bh_[0], bh_[1]);
                    MMA_BF16(acc[i][2 * p],     ah_[i], bl_[0], bl_[1]);
                    MMA_BF16(acc[i][2 * p],     al_[i], bh_[0], bh_[1]);
                    MMA_BF16(acc[i][2 * p + 1], ah_[i], bh_[2], bh_[3]);
                    MMA_BF16(acc[i][2 * p + 1], ah_[i], bl_[2], bl_[3]);
                    MMA_BF16(acc[i][2 * p + 1], al_[i], bh_[2], bh_[3]);
                }
            }
        }
    }

    // epilogue: kv = rstd*(acc - mu*c1) + c0
    int g = l >> 2, tig = l & 3;
#pragma unroll
    for (int i = 0; i < 2; i++) {
        int r0 = Mbase + wm * 32 + i * 16 + g;
        int r1 = r0 + 8;
        float mu0 = g_mu[r0], rstd0 = g_rstd[r0];
        float mu1 = g_mu[r1], rstd1 = g_rstd[r1];
#pragma unroll
        for (int j = 0; j < 8; j++) {
            int cn = wn * 64 + j * 8 + tig * 2;
            float c1a = g_c1[cn], c1b = g_c1[cn + 1];
            float c0a = g_c0[cn], c0b = g_c0[cn + 1];
            g_kv[(size_t)r0 * 128 + cn]     = rstd0 * (acc[i][j][0] - mu0 * c1a) + c0a;
            g_kv[(size_t)r0 * 128 + cn + 1] = rstd0 * (acc[i][j][1] - mu0 * c1b) + c0b;
            g_kv[(size_t)r1 * 128 + cn]     = rstd1 * (acc[i][j][2] - mu1 * c1a) + c0a;
            g_kv[(size_t)r1 * 128 + cn + 1] = rstd1 * (acc[i][j][3] - mu1 * c1b) + c0b;
        }
    }
}

// wkv = exp(-exp(tf) * sigmoid(k)) * v
__global__ __launch_bounds__(256) void k_wkv() {
    int idx = blockIdx.x * 256 + threadIdx.x;
    if (idx >= ROWS * DS) return;
    int r = idx / DS, d = idx - r * DS;
    float kk = g_kv[(size_t)r * (2 * DS) + d];
    float vv = g_kv[(size_t)r * (2 * DS) + DS + d];
    float sg = 1.0f / (1.0f + expf(-kk));
    g_wkv[idx] = expf(-g_etf[d] * sg) * vv;
}

// per-chunk scan: h = h*w + wkv; writes hs as bf16 hi/lo split
__global__ __launch_bounds__(64) void k_scan() {
    int chunk = blockIdx.x;
    int d = threadIdx.x;
    size_t base = (size_t)chunk * CHUNKL * DS + d;
    float w = g_w[d];
    float h = 0.0f;
#pragma unroll 4
    for (int t = 0; t < CHUNKL; t++) {
        size_t o = base + (size_t)t * DS;
        h = fmaf(h, w, g_wkv[o]);
        __nv_bfloat16 hh = __float2bfloat16(h);
        g_hsh[o] = hh;
        g_hsl[o] = __float2bfloat16(h - __bfloat162float(hh));
    }
}

// ================= GEMM3: out = hs @ WoT (K=64), single stage ==============
#define ROWB3  144                          // 64 bf16 + 8 pad = 144 bytes/row
#define TILE3B (128 * ROWB3)                // 18432
#define SMEM_MMA3 (4 * TILE3B)              // 73728

__global__ __launch_bounds__(256, 2) void k_mma3(float* __restrict__ out) {
    extern __shared__ char smraw[];
    uint32_t sb0 = smem_to_u32(smraw);
    int tid = threadIdx.x;
    int l = tid & 31, wid = tid >> 5;
    int wm = wid & 3;
    int wn = wid >> 2;
    int Mbase = blockIdx.y * 128;
    int Nbase = blockIdx.x * 128;

    float acc[2][8][4];
#pragma unroll
    for (int i = 0; i < 2; i++)
#pragma unroll
        for (int j = 0; j < 8; j++)
#pragma unroll
            for (int q = 0; q < 4; q++) acc[i][j][q] = 0.0f;

    uint32_t a_lane = (uint32_t)(((l & 7) + ((l >> 3) & 1) * 8) * ROWB3 + ((l >> 4) & 1) * 16);
    uint32_t b_lane = (uint32_t)(((l & 7) + ((l >> 4) & 1) * 8) * ROWB3 + ((l >> 3) & 1) * 16);

    // load all 4 tiles (A rows K=64, B rows K=64)
#pragma unroll
    for (int c = 0; c < 4; c++) {
        int ch = tid * 4 + c;                 // 0..1023
        int row = ch >> 3, seg = ch & 7;
        uint32_t off = (uint32_t)(row * ROWB3 + seg * 16);
        int ks = seg * 8;
        int ar = Mbase + row;
        CP_ASYNC16(sb0 + off,              (const char*)(g_hsh + (size_t)ar * DS + ks));
        CP_ASYNC16(sb0 + TILE3B + off,     (const char*)(g_hsl + (size_t)ar * DS + ks));
        int br = Nbase + row;
        CP_ASYNC16(sb0 + 2 * TILE3B + off, (const char*)(g_woth + (size_t)br * DS + ks));
        CP_ASYNC16(sb0 + 3 * TILE3B + off, (const char*)(g_wotl + (size_t)br * DS + ks));
    }
    CP_COMMIT();
    CP_WAIT0();
    __syncthreads();

#pragma unroll
    for (int c = 0; c < 4; c++) {            // 4 k16 chunks
        uint32_t kkB = (uint32_t)(c * 32);
        uint32_t ah_[2][4], al_[2][4];
#pragma unroll
        for (int i = 0; i < 2; i++) {
            uint32_t aaddr = sb0 + (uint32_t)((wm * 32 + i * 16) * ROWB3) + kkB + a_lane;
            LDSM4(ah_[i], aaddr);
            LDSM4(al_[i], aaddr + TILE3B);
        }
#pragma unroll
        for (int p = 0; p < 4; p++) {
            uint32_t baddr = sb0 + 2 * TILE3B + (uint32_t)((wn * 64 + p * 16) * ROWB3) + kkB + b_lane;
            uint32_t bh_[4], bl_[4];
            LDSM4(bh_, baddr);
            LDSM4(bl_, baddr + TILE3B);
#pragma unroll
            for (int i = 0; i < 2; i++) {
                MMA_BF16(acc[i][2 * p],     ah_[i], bh_[0], bh_[1]);
                MMA_BF16(acc[i][2 * p],     ah_[i], bl_[0], bl_[1]);
                MMA_BF16(acc[i][2 * p],     al_[i], bh_[0], bh_[1]);
                MMA_BF16(acc[i][2 * p + 1], ah_[i], bh_[2], bh_[3]);
                MMA_BF16(acc[i][2 * p + 1], ah_[i], bl_[2], bl_[3]);
                MMA_BF16(acc[i][2 * p + 1], al_[i], bh_[2], bh_[3]);
            }
        }
    }

    // epilogue: plain store
    int g = l >> 2, tig = l & 3;
#pragma unroll
    for (int i = 0; i < 2; i++) {
        int r0 = Mbase + wm * 32 + i * 16 + g;
        int r1 = r0 + 8;
#pragma unroll
        for (int j = 0; j < 8; j++) {
            int cn = Nbase + wn * 64 + j * 8 + tig * 2;
            size_t o00 = (size_t)r0 * DA + cn;
            size_t o10 = (size_t)r1 * DA + cn;
            out[o00]     = acc[i][j][0];
            out[o00 + 1] = acc[i][j][1];
            out[o10]     = acc[i][j][2];
            out[o10 + 1] = acc[i][j][3];
        }
    }
}

// last_state
__global__ __launch_bounds__(256) void k_last(float* __restrict__ ls) {
    int b  = blockIdx.x;
    int tg = threadIdx.x >> 6;
    int d  = threadIdx.x & 63;
    float acc = 0.0f;
    const float* wb = g_wkv + (size_t)b * Tn * DS;
    for (int t = tg; t < Tn; t += 4) {
        int c = t >> 7, j = t & 127;
        float kk = g_coef2[(NCHUNK - 1 - c) * DS + d] * g_coef[(CHUNKL - 1 - j) * DS + d];
        acc = fmaf(kk, wb[(size_t)t * DS + d], acc);
    }
    __shared__ float red[4][64];
    red[tg][d] = acc;
    __syncthreads();
    if (tg == 0)
        ls[b * DS + d] = red[0][d] + red[1][d] + red[2][d] + red[3][d];
}

// ---------------- launch ----------------
extern "C" void kernel_launch(void* const* d_in, const int* in_sizes, int n_in,
                              void* d_out, int out_size) {
    const float* x   = (const float*)d_in[0];
    const float* td  = (const float*)d_in[1];
    const float* tf  = (const float*)d_in[2];
    const float* Wk  = (const float*)d_in[3];
    const float* Wv  = (const float*)d_in[4];
    const float* Wo  = (const float*)d_in[5];
    const float* Wsh = (const float*)d_in[6];
    const float* sg  = (const float*)d_in[7];
    const float* lng = (const float*)d_in[8];
    const float* lnb = (const float*)d_in[9];
    float* out = (float*)d_out;

    static int smem_set = 0;
    if (!smem_set) {
        cudaFuncSetAttribute(k_mma1, cudaFuncAttributeMaxDynamicSharedMemorySize, SMEM_MMA1);
        cudaFuncSetAttribute(k_mma2, cudaFuncAttributeMaxDynamicSharedMemorySize, SMEM_MMA1);
        cudaFuncSetAttribute(k_mma3, cudaFuncAttributeMaxDynamicSharedMemorySize, SMEM_MMA3);
        smem_set = 1;
    }

    k_prep<<<1, 64>>>(td, tf);
    k_split<<<(int)((size_t)ROWS * DA / 4 / 256), 256>>>(x);
    {
        dim3 gw(DA / 32, DA / 32);
        k_wsplit<<<gw, 256>>>(Wsh);
    }
    k_w2split<<<128 * DA / 256, 256>>>(Wk, Wv);
    k_wosplit<<<DA * DS / 256, 256>>>(Wo);
    k_cvec<<<128, 256>>>(Wk, Wv, lng, lnb);
    {
        dim3 g1(DA / 128, ROWS / 128);
        k_mma1<<<g1, 256, SMEM_MMA1>>>(x, sg, lng);
    }
    k_lnfin<<<ROWS / 256, 256>>>();
    {
        dim3 g2(1, ROWS / 128);
        k_mma2<<<g2, 256, SMEM_MMA1>>>();
    }
    k_wkv<<<(ROWS * DS + 255) / 256, 256>>>();
    k_scan<<<Bn * NCHUNK, 64>>>();
    {
        dim3 g3(DA / 128, ROWS / 128);
        k_mma3<<<g3, 256, SMEM_MMA3>>>(out);
    }
    if (out_size >= ROWS * DA + Bn * DS) {
        k_last<<<Bn, 256>>>(out + (size_t)ROWS * DA);
    }
}

// round 8
// speedup vs baseline: 2.3591x; 1.2141x over previous
#include <cuda_runtime.h>
#include <cuda_bf16.h>
#include <math.h>
#include <stdint.h>

// Problem constants
#define Bn     4
#define Tn     8192
#define DA     1024
#define DS     64
#define CHUNKL 128
#define NCHUNK 64            // Tn / CHUNKL
#define ROWS   (Bn * Tn)     // 32768
#define LN_EPS 1e-5f

// ---------------- scratch (__device__ globals; no allocation) ----------------
__device__ float g_kv[(size_t)ROWS * 2 * DS];   // 16 MB  (k | v per row)
__device__ float g_mu[ROWS];
__device__ float g_rstd[ROWS];
__device__ float g_w[DS];
__device__ float g_etf[DS];
__device__ float g_coef[CHUNKL * DS];
__device__ float g_coef2[NCHUNK * DS];
__device__ float g_c1[2 * DS];                  // lng @ [Wk|Wv]
__device__ float g_c0[2 * DS];                  // lnb @ [Wk|Wv]
__device__ float g_psum[16 * ROWS];             // partial row sums of x_shift
__device__ float g_psum2[16 * ROWS];            // partial row sums of x_shift^2
__device__ float g_cdot[Bn * NCHUNK * DS];      // per-chunk coef-weighted wkv dots
// bf16 split operands
__device__ __nv_bfloat16 g_xh[(size_t)ROWS * DA];   // x hi
__device__ __nv_bfloat16 g_xl[(size_t)ROWS * DA];   // x lo
__device__ __nv_bfloat16 g_uh[(size_t)ROWS * DA];   // u = x_shift*lng hi
__device__ __nv_bfloat16 g_ul[(size_t)ROWS * DA];   // u lo
__device__ __nv_bfloat16 g_wth[(size_t)DA * DA];    // Wshift^T hi [n][k]
__device__ __nv_bfloat16 g_wtl[(size_t)DA * DA];    // Wshift^T lo
__device__ __nv_bfloat16 g_w2th[(size_t)128 * DA];  // [Wk|Wv]^T hi [n][k]
__device__ __nv_bfloat16 g_w2tl[(size_t)128 * DA];
__device__ __nv_bfloat16 g_woth[(size_t)DA * DS];   // Wo^T hi [n][k]
__device__ __nv_bfloat16 g_wotl[(size_t)DA * DS];
__device__ __nv_bfloat16 g_hsh[(size_t)ROWS * DS];  // hs hi
__device__ __nv_bfloat16 g_hsl[(size_t)ROWS * DS];  // hs lo

// ======================= PTX helpers =======================
__device__ __forceinline__ uint32_t smem_to_u32(const void* p) {
    uint32_t a;
    asm("{ .reg .u64 t; cvta.to.shared.u64 t, %1; cvt.u32.u64 %0, t; }" : "=r"(a) : "l"(p));
    return a;
}

#define CP_ASYNC16(dst, src) asm volatile("cp.async.cg.shared.global [%0], [%1], 16;" :: "r"(dst), "l"(src) : "memory")
#define CP_COMMIT()          asm volatile("cp.async.commit_group;" ::: "memory")
#define CP_WAIT0()           asm volatile("cp.async.wait_group 0;" ::: "memory")

#define LDSM4(r, a) \
    asm volatile("ldmatrix.sync.aligned.m8n8.x4.shared.b16 {%0,%1,%2,%3}, [%4];" \
        : "=r"((r)[0]), "=r"((r)[1]), "=r"((r)[2]), "=r"((r)[3]) : "r"(a))

#define MMA_BF16(c, a, b0, b1) \
    asm volatile("mma.sync.aligned.m16n8k16.row.col.f32.bf16.bf16.f32 " \
        "{%0,%1,%2,%3}, {%4,%5,%6,%7}, {%8,%9}, {%0,%1,%2,%3};" \
        : "+f"((c)[0]), "+f"((c)[1]), "+f"((c)[2]), "+f"((c)[3]) \
        : "r"((a)[0]), "r"((a)[1]), "r"((a)[2]), "r"((a)[3]), "r"(b0), "r"(b1))

__device__ __forceinline__ float sigm(float v) { return 1.0f / (1.0f + expf(-v)); }

// ---------------- prep ----------------
__global__ void k_prep(const float* __restrict__ td, const float* __restrict__ tf) {
    int d = threadIdx.x;
    if (d >= DS) return;
    float w = expf(td[d]);
    g_w[d]   = w;
    g_etf[d] = expf(tf[d]);

    float c[CHUNKL];
    c[0] = 1.0f;
    for (int i = 1; i < CHUNKL; i++) c[i] = 0.0f;
    for (int s = 1; s < CHUNKL; s++)
        for (int i = CHUNKL - 1; i >= s; i--)
            c[i] += w * c[i - s];
    for (int i = 0; i < CHUNKL; i++) g_coef[i * DS + d] = c[i];

    float W = expf((float)CHUNKL * td[d]);
    float c2[NCHUNK];
    c2[0] = 1.0f;
    for (int i = 1; i < NCHUNK; i++) c2[i] = 0.0f;
    for (int s = 1; s < NCHUNK; s++)
        for (int i = NCHUNK - 1; i >= s; i--)
            c2[i] += W * c2[i - s];
    for (int i = 0; i < NCHUNK; i++) g_coef2[i * DS + d] = c2[i];
}

// ---------------- x -> bf16 hi/lo split ----------------
__global__ __launch_bounds__(256) void k_split(const float* __restrict__ x) {
    size_t idx = (size_t)blockIdx.x * 256 + threadIdx.x;   // float4 index
    float4 v = reinterpret_cast<const float4*>(x)[idx];
    __nv_bfloat16 h0 = __float2bfloat16(v.x), h1 = __float2bfloat16(v.y);
    __nv_bfloat16 h2 = __float2bfloat16(v.z), h3 = __float2bfloat16(v.w);
    __nv_bfloat162* xh2 = reinterpret_cast<__nv_bfloat162*>(g_xh);
    __nv_bfloat162* xl2 = reinterpret_cast<__nv_bfloat162*>(g_xl);
    __nv_bfloat162 a, b;
    a.x = h0; a.y = h1; b.x = h2; b.y = h3;
    xh2[idx * 2] = a; xh2[idx * 2 + 1] = b;
    a.x = __float2bfloat16(v.x - __bfloat162float(h0));
    a.y = __float2bfloat16(v.y - __bfloat162float(h1));
    b.x = __float2bfloat16(v.z - __bfloat162float(h2));
    b.y = __float2bfloat16(v.w - __bfloat162float(h3));
    xl2[idx * 2] = a; xl2[idx * 2 + 1] = b;
}

// ---------------- Wshift transpose + bf16 split: WT[n][k] ----------------
__global__ __launch_bounds__(256) void k_wsplit(const float* __restrict__ Wsh) {
    __shared__ float t[32][33];
    int k0 = blockIdx.y * 32, n0 = blockIdx.x * 32;
    int tx = threadIdx.x & 31, ty = threadIdx.x >> 5;   // 32 x 8
#pragma unroll
    for (int j = 0; j < 4; j++) {
        int row = ty + j * 8;
        t[row][tx] = Wsh[(size_t)(k0 + row) * DA + n0 + tx];
    }
    __syncthreads();
#pragma unroll
    for (int j = 0; j < 4; j++) {
        int row = ty + j * 8;                 // n-offset
        float v = t[tx][row];
        __nv_bfloat16 h = __float2bfloat16(v);
        __nv_bfloat16 l = __float2bfloat16(v - __bfloat162float(h));
        size_t o = (size_t)(n0 + row) * DA + k0 + tx;
        g_wth[o] = h;
        g_wtl[o] = l;
    }
}

// ---------------- [Wk|Wv]^T split: W2T[n][k], n<64 -> Wk, n>=64 -> Wv -------
__global__ __launch_bounds__(256) void k_w2split(const float* __restrict__ Wk,
                                                 const float* __restrict__ Wv) {
    int idx = blockIdx.x * 256 + threadIdx.x;    // 128*1024
    int n = idx >> 10, k = idx & 1023;
    float v = (n < DS) ? Wk[(size_t)k * DS + n] : Wv[(size_t)k * DS + (n - DS)];
    __nv_bfloat16 h = __float2bfloat16(v);
    g_w2th[idx] = h;
    g_w2tl[idx] = __float2bfloat16(v - __bfloat162float(h));
}

// ---------------- Wo^T split: WoT[n][k] = Wo[k][n] ----------------
__global__ __launch_bounds__(256) void k_wosplit(const float* __restrict__ Wo) {
    int idx = blockIdx.x * 256 + threadIdx.x;    // 1024*64
    int n = idx >> 6, k = idx & 63;
    float v = Wo[(size_t)k * DA + n];
    __nv_bfloat16 h = __float2bfloat16(v);
    g_woth[idx] = h;
    g_wotl[idx] = __float2bfloat16(v - __bfloat162float(h));
}

// ---------------- c1 = lng @ [Wk|Wv], c0 = lnb @ [Wk|Wv] ----------------
__global__ __launch_bounds__(256) void k_cvec(const float* __restrict__ Wk,
                                              const float* __restrict__ Wv,
                                              const float* __restrict__ lng,
                                              const float* __restrict__ lnb) {
    int n = blockIdx.x;                           // 0..127
    const float* W = (n < DS) ? Wk : Wv;
    int col = (n < DS) ? n : n - DS;
    float s1 = 0.0f, s0 = 0.0f;
    for (int k = threadIdx.x; k < DA; k += 256) {
        float w = W[(size_t)k * DS + col];
        s1 = fmaf(lng[k], w, s1);
        s0 = fmaf(lnb[k], w, s0);
    }
#pragma unroll
    for (int o = 16; o > 0; o >>= 1) {
        s1 += __shfl_down_sync(0xffffffffu, s1, o);
        s0 += __shfl_down_sync(0xffffffffu, s0, o);
    }
    __shared__ float a1[8], a0[8];
    int w = threadIdx.x >> 5;
    if ((threadIdx.x & 31) == 0) { a1[w] = s1; a0[w] = s0; }
    __syncthreads();
    if (threadIdx.x == 0) {
        float S1 = 0.0f, S0 = 0.0f;
#pragma unroll
        for (int i = 0; i < 8; i++) { S1 += a1[i]; S0 += a0[i]; }
        g_c1[n] = S1;
        g_c0[n] = S0;
    }
}

// ================= GEMM1: mma.sync bf16 3-term split =================
#define ROWB   80                           // 32 bf16 + 8 pad = 80 bytes/row
#define TILEB  (128 * ROWB)                 // 10240
#define STAGEB (4 * TILEB)                  // 40960 (Ah, Al, Bh, Bl)
#define SMEM_MMA1 (2 * STAGEB)              // 81920, double buffered
#define KSTAGES 32                          // K=1024 / 32

__global__ __launch_bounds__(256, 2) void k_mma1(const float* __restrict__ x,
                                                 const float* __restrict__ sgate,
                                                 const float* __restrict__ lng) {
    extern __shared__ char smraw[];
    uint32_t sb0 = smem_to_u32(smraw);
    int tid = threadIdx.x;
    int l = tid & 31, wid = tid >> 5;
    int wm = wid & 3;          // warp row (32 M-rows each)
    int wn = wid >> 2;         // warp col (64 N-cols each)
    int Mbase = blockIdx.y * 128;
    int Nbase = blockIdx.x * 128;

    float acc[2][8][4];
#pragma unroll
    for (int i = 0; i < 2; i++)
#pragma unroll
        for (int j = 0; j < 8; j++)
#pragma unroll
            for (int q = 0; q < 4; q++) acc[i][j][q] = 0.0f;

    uint32_t a_lane = (uint32_t)(((l & 7) + ((l >> 3) & 1) * 8) * ROWB + ((l >> 4) & 1) * 16);
    uint32_t b_lane = (uint32_t)(((l & 7) + ((l >> 4) & 1) * 8) * ROWB + ((l >> 3) & 1) * 16);

    auto load_stage = [&](int s) {
        uint32_t dst = sb0 + (uint32_t)(s & 1) * STAGEB;
        int kb = s * 32;
#pragma unroll
        for (int c = 0; c < 2; c++) {
            int ch = tid * 2 + c;
            int row = ch >> 2, seg = ch & 3;
            uint32_t off = (uint32_t)(row * ROWB + seg * 16);
            int ks = kb + seg * 8;
            int ar = (Mbase + row) ^ 4096;
            CP_ASYNC16(dst + off,             (const char*)(g_xh + (size_t)ar * DA + ks));
            CP_ASYNC16(dst + TILEB + off,     (const char*)(g_xl + (size_t)ar * DA + ks));
            int br = Nbase + row;
            CP_ASYNC16(dst + 2 * TILEB + off, (const char*)(g_wth + (size_t)br * DA + ks));
            CP_ASYNC16(dst + 3 * TILEB + off, (const char*)(g_wtl + (size_t)br * DA + ks));
        }
        CP_COMMIT();
    };

    load_stage(0);
    for (int s = 0; s < KSTAGES; s++) {
        CP_WAIT0();
        __syncthreads();
        if (s + 1 < KSTAGES) load_stage(s + 1);

        uint32_t base = sb0 + (uint32_t)(s & 1) * STAGEB;
#pragma unroll
        for (int h = 0; h < 2; h++) {
            uint32_t kkB = (uint32_t)(h * 32);
            uint32_t ah_[2][4], al_[2][4];
#pragma unroll
            for (int i = 0; i < 2; i++) {
                uint32_t aaddr = base + (uint32_t)((wm * 32 + i * 16) * ROWB) + kkB + a_lane;
                LDSM4(ah_[i], aaddr);
                LDSM4(al_[i], aaddr + TILEB);
            }
#pragma unroll
            for (int p = 0; p < 4; p++) {
                uint32_t baddr = base + 2 * TILEB + (uint32_t)((wn * 64 + p * 16) * ROWB) + kkB + b_lane;
                uint32_t bh_[4], bl_[4];
                LDSM4(bh_, baddr);
                LDSM4(bl_, baddr + TILEB);
#pragma unroll
                for (int i = 0; i < 2; i++) {
                    MMA_BF16(acc[i][2 * p],     ah_[i], bh_[0], bh_[1]);
                    MMA_BF16(acc[i][2 * p],     ah_[i], bl_[0], bl_[1]);
                    MMA_BF16(acc[i][2 * p],     al_[i], bh_[0], bh_[1]);
                    MMA_BF16(acc[i][2 * p + 1], ah_[i], bh_[2], bh_[3]);
                    MMA_BF16(acc[i][2 * p + 1], ah_[i], bl_[2], bl_[3]);
                    MMA_BF16(acc[i][2 * p + 1], al_[i], bh_[2], bh_[3]);
                }
            }
        }
    }

    // epilogue: gate mix, write u = x_shift*lng as bf16 split, partial LN sums
    int g = l >> 2, tig = l & 3;
    int cb = blockIdx.x * 2 + wn;           // 0..15 partial-sum slot
#pragma unroll
    for (int i = 0; i < 2; i++) {
        int r0 = Mbase + wm * 32 + i * 16 + g;
        int r1 = r0 + 8;
        float rs0 = 0.0f, rq0 = 0.0f, rs1 = 0.0f, rq1 = 0.0f;
#pragma unroll
        for (int j = 0; j < 8; j++) {
            int cn = Nbase + wn * 64 + j * 8 + tig * 2;
            float g0 = sigm(sgate[cn]);
            float g1 = sigm(sgate[cn + 1]);
            size_t o00 = (size_t)r0 * DA + cn;
            size_t o10 = (size_t)r1 * DA + cn;
            float xs00 = acc[i][j][0] * g0 + x[o00]     * (1.0f - g0);
            float xs01 = acc[i][j][1] * g1 + x[o00 + 1] * (1.0f - g1);
            float xs10 = acc[i][j][2] * g0 + x[o10]     * (1.0f - g0);
            float xs11 = acc[i][j][3] * g1 + x[o10 + 1] * (1.0f - g1);
            rs0 += xs00 + xs01;  rq0 += xs00 * xs00 + xs01 * xs01;
            rs1 += xs10 + xs11;  rq1 += xs10 * xs10 + xs11 * xs11;
            float ln0 = lng[cn], ln1 = lng[cn + 1];
            float u00 = xs00 * ln0, u01 = xs01 * ln1;
            float u10 = xs10 * ln0, u11 = xs11 * ln1;
            __nv_bfloat162 hh, ll;
            hh.x = __float2bfloat16(u00); hh.y = __float2bfloat16(u01);
            ll.x = __float2bfloat16(u00 - __bfloat162float(hh.x));
            ll.y = __float2bfloat16(u01 - __bfloat162float(hh.y));
            *reinterpret_cast<__nv_bfloat162*>(g_uh + o00) = hh;
            *reinterpret_cast<__nv_bfloat162*>(g_ul + o00) = ll;
            hh.x = __float2bfloat16(u10); hh.y = __float2bfloat16(u11);
            ll.x = __float2bfloat16(u10 - __bfloat162float(hh.x));
            ll.y = __float2bfloat16(u11 - __bfloat162float(hh.y));
            *reinterpret_cast<__nv_bfloat162*>(g_uh + o10) = hh;
            *reinterpret_cast<__nv_bfloat162*>(g_ul + o10) = ll;
        }
        // reduce across the 4-lane quad (tig)
        rs0 += __shfl_xor_sync(0xffffffffu, rs0, 1); rs0 += __shfl_xor_sync(0xffffffffu, rs0, 2);
        rq0 += __shfl_xor_sync(0xffffffffu, rq0, 1); rq0 += __shfl_xor_sync(0xffffffffu, rq0, 2);
        rs1 += __shfl_xor_sync(0xffffffffu, rs1, 1); rs1 += __shfl_xor_sync(0xffffffffu, rs1, 2);
        rq1 += __shfl_xor_sync(0xffffffffu, rq1, 1); rq1 += __shfl_xor_sync(0xffffffffu, rq1, 2);
        if (tig == 0) {
            g_psum [cb * ROWS + r0] = rs0;
            g_psum2[cb * ROWS + r0] = rq0;
            g_psum [cb * ROWS + r1] = rs1;
            g_psum2[cb * ROWS + r1] = rq1;
        }
    }
}

// ---------------- LN finalize ----------------
__global__ __launch_bounds__(256) void k_lnfin() {
    int r = blockIdx.x * 256 + threadIdx.x;
    float s = 0.0f, s2 = 0.0f;
#pragma unroll
    for (int cb = 0; cb < 16; cb++) {
        s  += g_psum [cb * ROWS + r];
        s2 += g_psum2[cb * ROWS + r];
    }
    float mu  = s * (1.0f / (float)DA);
    float var = s2 * (1.0f / (float)DA) - mu * mu;
    g_mu[r]   = mu;
    g_rstd[r] = rsqrtf(var + LN_EPS);
}

// ================= GEMM2: [k|v] = u @ W2T with affine LN correction ========
__global__ __launch_bounds__(256, 2) void k_mma2() {
    extern __shared__ char smraw[];
    uint32_t sb0 = smem_to_u32(smraw);
    int tid = threadIdx.x;
    int l = tid & 31, wid = tid >> 5;
    int wm = wid & 3;
    int wn = wid >> 2;
    int Mbase = blockIdx.y * 128;

    float acc[2][8][4];
#pragma unroll
    for (int i = 0; i < 2; i++)
#pragma unroll
        for (int j = 0; j < 8; j++)
#pragma unroll
            for (int q = 0; q < 4; q++) acc[i][j][q] = 0.0f;

    uint32_t a_lane = (uint32_t)(((l & 7) + ((l >> 3) & 1) * 8) * ROWB + ((l >> 4) & 1) * 16);
    uint32_t b_lane = (uint32_t)(((l & 7) + ((l >> 4) & 1) * 8) * ROWB + ((l >> 3) & 1) * 16);

    auto load_stage = [&](int s) {
        uint32_t dst = sb0 + (uint32_t)(s & 1) * STAGEB;
        int kb = s * 32;
#pragma unroll
        for (int c = 0; c < 2; c++) {
            int ch = tid * 2 + c;
            int row = ch >> 2, seg = ch & 3;
            uint32_t off = (uint32_t)(row * ROWB + seg * 16);
            int ks = kb + seg * 8;
            int ar = Mbase + row;
            CP_ASYNC16(dst + off,             (const char*)(g_uh + (size_t)ar * DA + ks));
            CP_ASYNC16(dst + TILEB + off,     (const char*)(g_ul + (size_t)ar * DA + ks));
            CP_ASYNC16(dst + 2 * TILEB + off, (const char*)(g_w2th + (size_t)row * DA + ks));
            CP_ASYNC16(dst + 3 * TILEB + off, (const char*)(g_w2tl + (size_t)row * DA + ks));
        }
        CP_COMMIT();
    };

    load_stage(0);
    for (int s = 0; s < KSTAGES; s++) {
        CP_WAIT0();
        __syncthreads();
        if (s + 1 < KSTAGES) load_stage(s + 1);

        uint32_t base = sb0 + (uint32_t)(s & 1) * STAGEB;
#pragma unroll
        for (int h = 0; h < 2; h++) {
            uint32_t kkB = (uint32_t)(h * 32);
            uint32_t ah_[2][4], al_[2][4];
#pragma unroll
            for (int i = 0; i < 2; i++) {
                uint32_t aaddr = base + (uint32_t)((wm * 32 + i * 16) * ROWB) + kkB + a_lane;
                LDSM4(ah_[i], aaddr);
                LDSM4(al_[i], aaddr + TILEB);
            }
#pragma unroll
            for (int p = 0; p < 4; p++) {
                uint32_t baddr = base + 2 * TILEB + (uint32_t)((wn * 64 + p * 16) * ROWB) + kkB + b_lane;
                uint32_t bh_[4], bl_[4];
                LDSM4(bh_, baddr);
                LDSM4(bl_, baddr + TILEB);
#pragma unroll
                for (int i = 0; i < 2; i++) {
                    MMA_BF16(acc[i][2 * p],     ah_[i], bh_[0], bh_[1]);
                    MMA_BF16(acc[i][2 * p],     ah_[i], bl_[0], bl_[1]);
                    MMA_BF16(acc[i][2 * p],     al_[i], bh_[0], bh_[1]);
                    MMA_BF16(acc[i][2 * p + 1], ah_[i], bh_[2], bh_[3]);
                    MMA_BF16(acc[i][2 * p + 1], ah_[i], bl_[2], bl_[3]);
                    MMA_BF16(acc[i][2 * p + 1], al_[i], bh_[2], bh_[3]);
                }
            }
        }
    }

    // epilogue: kv = rstd*(acc - mu*c1) + c0
    int g = l >> 2, tig = l & 3;
#pragma unroll
    for (int i = 0; i < 2; i++) {
        int r0 = Mbase + wm * 32 + i * 16 + g;
        int r1 = r0 + 8;
        float mu0 = g_mu[r0], rstd0 = g_rstd[r0];
        float mu1 = g_mu[r1], rstd1 = g_rstd[r1];
#pragma unroll
        for (int j = 0; j < 8; j++) {
            int cn = wn * 64 + j * 8 + tig * 2;
            float c1a = g_c1[cn], c1b = g_c1[cn + 1];
            float c0a = g_c0[cn], c0b = g_c0[cn + 1];
            g_kv[(size_t)r0 * 128 + cn]     = rstd0 * (acc[i][j][0] - mu0 * c1a) + c0a;
            g_kv[(size_t)r0 * 128 + cn + 1] = rstd0 * (acc[i][j][1] - mu0 * c1b) + c0b;
            g_kv[(size_t)r1 * 128 + cn]     = rstd1 * (acc[i][j][2] - mu1 * c1a) + c0a;
            g_kv[(size_t)r1 * 128 + cn + 1] = rstd1 * (acc[i][j][3] - mu1 * c1b) + c0b;
        }
    }
}

// ====== fused wkv + per-chunk scan + last-state partial dot ======
// thread (chunk, d): reads k,v from g_kv, computes wkv inline, scans h,
// writes hs bf16 split, and accumulates lacc = sum_t coef[127-t]*wkv.
__global__ __launch_bounds__(64) void k_scan2() {
    int chunk = blockIdx.x;              // 0 .. Bn*NCHUNK-1
    int d = threadIdx.x;
    size_t kvbase = (size_t)chunk * CHUNKL * 128 + d;   // g_kv row stride 128
    size_t hbase  = (size_t)chunk * CHUNKL * DS + d;
    float w   = g_w[d];
    float etf = g_etf[d];
    float h = 0.0f, lacc = 0.0f;
#pragma unroll 4
    for (int t = 0; t < CHUNKL; t++) {
        float kk = g_kv[kvbase + (size_t)t * 128];
        float vv = g_kv[kvbase + (size_t)t * 128 + 64];
        float sg = 1.0f / (1.0f + expf(-kk));
        float wkv = expf(-etf * sg) * vv;
        h = fmaf(h, w, wkv);
        lacc = fmaf(g_coef[(CHUNKL - 1 - t) * DS + d], wkv, lacc);
        __nv_bfloat16 hh = __float2bfloat16(h);
        g_hsh[hbase + (size_t)t * DS] = hh;
        g_hsl[hbase + (size_t)t * DS] = __float2bfloat16(h - __bfloat162float(hh));
    }
    g_cdot[chunk * DS + d] = lacc;
}

// last_state finalize: ls[b,d] = sum_c coef2[63-c,d] * cdot[b*64+c,d]
__global__ __launch_bounds__(256) void k_lastfin(float* __restrict__ ls) {
    int b = threadIdx.x >> 6;            // 0..3
    int d = threadIdx.x & 63;
    float s = 0.0f;
#pragma unroll 4
    for (int c = 0; c < NCHUNK; c++)
        s = fmaf(g_coef2[(NCHUNK - 1 - c) * DS + d], g_cdot[(b * NCHUNK + c) * DS + d], s);
    ls[b * DS + d] = s;
}

// ================= GEMM3: out = hs @ WoT (K=64), single stage ==============
#define ROWB3  144                          // 64 bf16 + 8 pad = 144 bytes/row
#define TILE3B (128 * ROWB3)                // 18432
#define SMEM_MMA3 (4 * TILE3B)              // 73728

__global__ __launch_bounds__(256, 2) void k_mma3(float* __restrict__ out) {
    extern __shared__ char smraw[];
    uint32_t sb0 = smem_to_u32(smraw);
    int tid = threadIdx.x;
    int l = tid & 31, wid = tid >> 5;
    int wm = wid & 3;
    int wn = wid >> 2;
    int Mbase = blockIdx.y * 128;
    int Nbase = blockIdx.x * 128;

    float acc[2][8][4];
#pragma unroll
    for (int i = 0; i < 2; i++)
#pragma unroll
        for (int j = 0; j < 8; j++)
#pragma unroll
            for (int q = 0; q < 4; q++) acc[i][j][q] = 0.0f;

    uint32_t a_lane = (uint32_t)(((l & 7) + ((l >> 3) & 1) * 8) * ROWB3 + ((l >> 4) & 1) * 16);
    uint32_t b_lane = (uint32_t)(((l & 7) + ((l >> 4) & 1) * 8) * ROWB3 + ((l >> 3) & 1) * 16);

#pragma unroll
    for (int c = 0; c < 4; c++) {
        int ch = tid * 4 + c;                 // 0..1023
        int row = ch >> 3, seg = ch & 7;
        uint32_t off = (uint32_t)(row * ROWB3 + seg * 16);
        int ks = seg * 8;
        int ar = Mbase + row;
        CP_ASYNC16(sb0 + off,              (const char*)(g_hsh + (size_t)ar * DS + ks));
        CP_ASYNC16(sb0 + TILE3B + off,     (const char*)(g_hsl + (size_t)ar * DS + ks));
        int br = Nbase + row;
        CP_ASYNC16(sb0 + 2 * TILE3B + off, (const char*)(g_woth + (size_t)br * DS + ks));
        CP_ASYNC16(sb0 + 3 * TILE3B + off, (const char*)(g_wotl + (size_t)br * DS + ks));
    }
    CP_COMMIT();
    CP_WAIT0();
    __syncthreads();

#pragma unroll
    for (int c = 0; c < 4; c++) {            // 4 k16 chunks
        uint32_t kkB = (uint32_t)(c * 32);
        uint32_t ah_[2][4], al_[2][4];
#pragma unroll
        for (int i = 0; i < 2; i++) {
            uint32_t aaddr = sb0 + (uint32_t)((wm * 32 + i * 16) * ROWB3) + kkB + a_lane;
            LDSM4(ah_[i], aaddr);
            LDSM4(al_[i], aaddr + TILE3B);
        }
#pragma unroll
        for (int p = 0; p < 4; p++) {
            uint32_t baddr = sb0 + 2 * TILE3B + (uint32_t)((wn * 64 + p * 16) * ROWB3) + kkB + b_lane;
            uint32_t bh_[4], bl_[4];
            LDSM4(bh_, baddr);
            LDSM4(bl_, baddr + TILE3B);
#pragma unroll
            for (int i = 0; i < 2; i++) {
                MMA_BF16(acc[i][2 * p],     ah_[i], bh_[0], bh_[1]);
                MMA_BF16(acc[i][2 * p],     ah_[i], bl_[0], bl_[1]);
                MMA_BF16(acc[i][2 * p],     al_[i], bh_[0], bh_[1]);
                MMA_BF16(acc[i][2 * p + 1], ah_[i], bh_[2], bh_[3]);
                MMA_BF16(acc[i][2 * p + 1], ah_[i], bl_[2], bl_[3]);
                MMA_BF16(acc[i][2 * p + 1], al_[i], bh_[2], bh_[3]);
            }
        }
    }

    // epilogue: plain store
    int g = l >> 2, tig = l & 3;
#pragma unroll
    for (int i = 0; i < 2; i++) {
        int r0 = Mbase + wm * 32 + i * 16 + g;
        int r1 = r0 + 8;
#pragma unroll
        for (int j = 0; j < 8; j++) {
            int cn = Nbase + wn * 64 + j * 8 + tig * 2;
            size_t o00 = (size_t)r0 * DA + cn;
            size_t o10 = (size_t)r1 * DA + cn;
            out[o00]     = acc[i][j][0];
            out[o00 + 1] = acc[i][j][1];
            out[o10]     = acc[i][j][2];
            out[o10 + 1] = acc[i][j][3];
        }
    }
}

// ---------------- launch ----------------
extern "C" void kernel_launch(void* const* d_in, const int* in_sizes, int n_in,
                              void* d_out, int out_size) {
    const float* x   = (const float*)d_in[0];
    const float* td  = (const float*)d_in[1];
    const float* tf  = (const float*)d_in[2];
    const float* Wk  = (const float*)d_in[3];
    const float* Wv  = (const float*)d_in[4];
    const float* Wo  = (const float*)d_in[5];
    const float* Wsh = (const float*)d_in[6];
    const float* sg  = (const float*)d_in[7];
    const float* lng = (const float*)d_in[8];
    const float* lnb = (const float*)d_in[9];
    float* out = (float*)d_out;

    static int smem_set = 0;
    if (!smem_set) {
        cudaFuncSetAttribute(k_mma1, cudaFuncAttributeMaxDynamicSharedMemorySize, SMEM_MMA1);
        cudaFuncSetAttribute(k_mma2, cudaFuncAttributeMaxDynamicSharedMemorySize, SMEM_MMA1);
        cudaFuncSetAttribute(k_mma3, cudaFuncAttributeMaxDynamicSharedMemorySize, SMEM_MMA3);
        smem_set = 1;
    }

    k_prep<<<1, 64>>>(td, tf);
    k_split<<<(int)((size_t)ROWS * DA / 4 / 256), 256>>>(x);
    {
        dim3 gw(DA / 32, DA / 32);
        k_wsplit<<<gw, 256>>>(Wsh);
    }
    k_w2split<<<128 * DA / 256, 256>>>(Wk, Wv);
    k_wosplit<<<DA * DS / 256, 256>>>(Wo);
    k_cvec<<<128, 256>>>(Wk, Wv, lng, lnb);
    {
        dim3 g1(DA / 128, ROWS / 128);
        k_mma1<<<g1, 256, SMEM_MMA1>>>(x, sg, lng);
    }
    k_lnfin<<<ROWS / 256, 256>>>();
    {
        dim3 g2(1, ROWS / 128);
        k_mma2<<<g2, 256, SMEM_MMA1>>>();
    }
    k_scan2<<<Bn * NCHUNK, 64>>>();
    {
        dim3 g3(DA / 128, ROWS / 128);
        k_mma3<<<g3, 256, SMEM_MMA3>>>(out);
    }
    if (out_size >= ROWS * DA + Bn * DS) {
        k_lastfin<<<1, 256>>>(out + (size_t)ROWS * DA);
    }
}